// round 10
// baseline (speedup 1.0000x reference)
#include <cuda_runtime.h>
#include <math.h>

#define TT 4096
#define EE 768
#define HH 12
#define DD 64
#define WIN 512
#define OUT_ELEMS (TT*EE)                 // 3145728
#define ATTN_ELEMS ((size_t)HH*TT*TT)     // 201326592

typedef unsigned long long ull;

// f32x2 packed-FMA helpers (sm_100+ PTX; ptxas never auto-fuses these)
#define PACK2(d, x)  asm("mov.b64 %0, {%1, %2};" : "=l"(d) : "f"(x), "f"(x))
#define FMA2(d, a, b) asm("fma.rn.f32x2 %0, %1, %2, %0;" : "+l"(d) : "l"(a), "l"(b))
#define UNPACK2(lo, hi, v) asm("mov.b64 {%0, %1}, %2;" : "=f"(lo), "=f"(hi) : "l"(v))

// ---------------- scratch (device globals: allocation-free) ----------------
__device__ __align__(16) float g_Q[TT*EE];
__device__ __align__(16) float g_K[TT*EE];
__device__ __align__(16) float g_V[TT*EE];
__device__ __align__(16) float g_ctx[TT*EE];
__device__ __align__(16) float g_d[HH*TT];

// ---------------- fp32 GEMM with f32x2: C[4096,768] = A[4096,768] @ W[768,768]
// BM=128, BN=64, BK=16, 256 threads, 8x4 micro-tile (4 cols = 2 f32x2 pairs).
__global__ __launch_bounds__(256) void sgemm_kernel(
    const float* __restrict__ A,
    const float* __restrict__ W0, const float* __restrict__ W1, const float* __restrict__ W2,
    float* __restrict__ Cout, int mode)
{
    const float* W;
    float* C;
    const float* Ain;
    if (mode == 0) {
        int z = blockIdx.z;
        W = (z == 0) ? W0 : (z == 1) ? W1 : W2;
        C = (z == 0) ? g_Q : (z == 1) ? g_K : g_V;
        Ain = A;
    } else {
        W = W0; C = Cout; Ain = g_ctx;
    }

    __shared__ float As[16][128];
    __shared__ float Ws[16][64];

    int tid = threadIdx.x;
    int tx = tid & 15, ty = tid >> 4;
    int n0 = blockIdx.x * 64;
    int m0 = blockIdx.y * 128;

    ull acc[8][2];
    #pragma unroll
    for (int r = 0; r < 8; r++) { acc[r][0] = 0ULL; acc[r][1] = 0ULL; }

    for (int k0 = 0; k0 < 768; k0 += 16) {
        #pragma unroll
        for (int it = 0; it < 2; it++) {
            int idx = tid + it * 256;
            int row = idx >> 2;
            int kq = (idx & 3) * 4;
            float4 v = *(const float4*)(Ain + (size_t)(m0 + row) * 768 + k0 + kq);
            As[kq + 0][row] = v.x;
            As[kq + 1][row] = v.y;
            As[kq + 2][row] = v.z;
            As[kq + 3][row] = v.w;
        }
        {
            int kk = tid >> 4;
            int nq = (tid & 15) * 4;
            *(float4*)&Ws[kk][nq] = *(const float4*)(W + (size_t)(k0 + kk) * 768 + n0 + nq);
        }
        __syncthreads();

        #pragma unroll
        for (int kk = 0; kk < 16; kk++) {
            float4 a0 = *(float4*)&As[kk][ty * 8];
            float4 a1 = *(float4*)&As[kk][ty * 8 + 4];
            ull Ap[8];
            PACK2(Ap[0], a0.x); PACK2(Ap[1], a0.y); PACK2(Ap[2], a0.z); PACK2(Ap[3], a0.w);
            PACK2(Ap[4], a1.x); PACK2(Ap[5], a1.y); PACK2(Ap[6], a1.z); PACK2(Ap[7], a1.w);
            ull b0 = *(const ull*)&Ws[kk][tx * 4];      // 16B-aligned
            ull b1 = *(const ull*)&Ws[kk][tx * 4 + 2];
            #pragma unroll
            for (int r = 0; r < 8; r++) {
                FMA2(acc[r][0], Ap[r], b0);
                FMA2(acc[r][1], Ap[r], b1);
            }
        }
        __syncthreads();
    }

    #pragma unroll
    for (int r = 0; r < 8; r++) {
        float4 v;
        UNPACK2(v.x, v.y, acc[r][0]);
        UNPACK2(v.z, v.w, acc[r][1]);
        *(float4*)(C + (size_t)(m0 + ty * 8 + r) * 768 + n0 + tx * 4) = v;
    }
}

// ---------------- d bias: d[h,t] = K[t]·u[h] - mean_t(K[t]·u[h]) ------------
__global__ __launch_bounds__(1024) void dbias_kernel(const float* __restrict__ u)
{
    int h = blockIdx.x, tid = threadIdx.x;
    __shared__ float su[64];
    __shared__ float red[32];
    if (tid < 64) su[tid] = u[h * 64 + tid];
    __syncthreads();

    float vals[4];
    float lsum = 0.f;
    #pragma unroll
    for (int j = 0; j < 4; j++) {
        int t = j * 1024 + tid;
        const float4* kp = (const float4*)(g_K + (size_t)t * 768 + h * 64);
        float dot = 0.f;
        #pragma unroll
        for (int q = 0; q < 16; q++) {
            float4 kv = kp[q];
            dot += kv.x * su[q * 4] + kv.y * su[q * 4 + 1] + kv.z * su[q * 4 + 2] + kv.w * su[q * 4 + 3];
        }
        vals[j] = dot;
        lsum += dot;
    }
    #pragma unroll
    for (int o = 16; o > 0; o >>= 1) lsum += __shfl_xor_sync(0xffffffffu, lsum, o);
    if ((tid & 31) == 0) red[tid >> 5] = lsum;
    __syncthreads();
    if (tid < 32) {
        float v = red[tid];
        #pragma unroll
        for (int o = 16; o > 0; o >>= 1) v += __shfl_xor_sync(0xffffffffu, v, o);
        if (tid == 0) red[0] = v * (1.0f / 4096.0f);
    }
    __syncthreads();
    float mean = red[0];
    #pragma unroll
    for (int j = 0; j < 4; j++)
        g_d[h * 4096 + j * 1024 + tid] = vals[j] - mean;
}

// ---------------- attention: 64 query rows per block -----------------------
// smem: sQq/sKq [64][65] row-major; sQkT/sKkT [64][66] d-major (transposed,
// even stride for LDS.64); sKkT reused row-major [64][66] as V tile in phase 3.
// sL 64x577, sd 576, rowS 64.
#define LW 577
#define SMEM_FLOATS (2*64*65 + 2*64*66 + 64*LW + 576 + 64)
#define SMEM_BYTES (SMEM_FLOATS * 4)

__global__ __launch_bounds__(256) void attn_kernel(
    const float* __restrict__ gates, float* __restrict__ attn_out)
{
    extern __shared__ float sm[];
    float (*sQq)[65] = (float(*)[65])sm;
    float (*sKq)[65] = sQq + 64;
    float (*sQkT)[66] = (float(*)[66])(sKq + 64);   // [d][col]
    float (*sKkT)[66] = sQkT + 64;                  // [d][col]; also V [row][col]
    float* sL = (float*)(sKkT + 64);      // 64 * 577
    float* sd = sL + 64 * LW;             // 576
    float* rowS = sd + 576;               // 64 (1/rowsum)

    int h = blockIdx.y;
    int t0 = blockIdx.x * 64;
    int tid = threadIdx.x;
    int sb = t0 - 512; if (sb < 0) sb = 0;
    int L = t0 + 64 - sb;                 // multiple of 64, <= 576

    // ---- fused zero-fill of this block's out-of-band attn region ----
    // rows [t0,t0+64) of head h: cols [0,sb) and [t0+64,TT). Fire-and-forget
    // stores; they drain on the idle DRAM path while we do FFMA below.
    {
        const float4 z4 = make_float4(0.f, 0.f, 0.f, 0.f);
        size_t rowbase = (size_t)h * TT * TT + (size_t)t0 * TT;
        int leftq = sb >> 2;                   // sb multiple of 64
        int right0 = t0 + 64;
        int rightq = (TT - right0) >> 2;
        for (int r = 0; r < 64; r++) {
            float4* bp = (float4*)(attn_out + rowbase + (size_t)r * TT);
            for (int c = tid; c < leftq; c += 256) bp[c] = z4;
            float4* rp4 = (float4*)(attn_out + rowbase + (size_t)r * TT + right0);
            for (int c = tid; c < rightq; c += 256) rp4[c] = z4;
        }
    }

    // gate softmax (every thread, cheap + uniform)
    float g0 = gates[h * 3 + 0], g1 = gates[h * 3 + 1], g2 = gates[h * 3 + 2];
    float gm = fmaxf(g0, fmaxf(g1, g2));
    float e0 = __expf(g0 - gm), e1 = __expf(g1 - gm), e2 = __expf(g2 - gm);
    float gi = 1.0f / (e0 + e1 + e2);
    float wstd = e0 * gi, wrec = e1 * gi, wdisc = e2 * gi;

    // load Q, K for query rows (row-major, scalar smem stores) + d band
    for (int i = tid; i < 64 * 16; i += 256) {
        int row = i >> 4;
        int c4 = (i & 15) * 4;
        float4 q = *(const float4*)(g_Q + (size_t)(t0 + row) * 768 + h * 64 + c4);
        float4 k = *(const float4*)(g_K + (size_t)(t0 + row) * 768 + h * 64 + c4);
        sQq[row][c4 + 0] = q.x; sQq[row][c4 + 1] = q.y; sQq[row][c4 + 2] = q.z; sQq[row][c4 + 3] = q.w;
        sKq[row][c4 + 0] = k.x; sKq[row][c4 + 1] = k.y; sKq[row][c4 + 2] = k.z; sKq[row][c4 + 3] = k.w;
    }
    for (int i = tid; i < L; i += 256) sd[i] = g_d[h * 4096 + sb + i];

    int tx = tid & 15, ty = tid >> 4;
    int i0 = ty * 4, j0 = tx * 4;
    int kt_lo = sb >> 6, kt_hi = t0 >> 6;

    // ---- phase 1: banded logits into sL ----
    for (int kt = kt_lo; kt <= kt_hi; kt++) {
        int s0 = kt * 64;
        __syncthreads();
        // load key-block Q,K transposed: sXkT[d][col] = X[s0+col][d]
        for (int i = tid; i < 64 * 16; i += 256) {
            int row = i >> 4;
            int c4 = (i & 15) * 4;
            float4 q = *(const float4*)(g_Q + (size_t)(s0 + row) * 768 + h * 64 + c4);
            float4 k = *(const float4*)(g_K + (size_t)(s0 + row) * 768 + h * 64 + c4);
            sQkT[c4 + 0][row] = q.x; sQkT[c4 + 1][row] = q.y; sQkT[c4 + 2][row] = q.z; sQkT[c4 + 3][row] = q.w;
            sKkT[c4 + 0][row] = k.x; sKkT[c4 + 1][row] = k.y; sKkT[c4 + 2][row] = k.z; sKkT[c4 + 3][row] = k.w;
        }
        __syncthreads();

        ull acc1[4][2], acc2[4][2];
        #pragma unroll
        for (int r = 0; r < 4; r++) {
            acc1[r][0] = 0ULL; acc1[r][1] = 0ULL;
            acc2[r][0] = 0ULL; acc2[r][1] = 0ULL;
        }

        #pragma unroll 8
        for (int d = 0; d < 64; d++) {
            ull Ap[4], KEp[4];
            #pragma unroll
            for (int r = 0; r < 4; r++) {
                PACK2(Ap[r],  sQq[i0 + r][d]);
                PACK2(KEp[r], sKq[i0 + r][d]);
            }
            ull B0  = *(const ull*)&sKkT[d][j0];      // (66*d + j0) even -> 8B aligned
            ull B1  = *(const ull*)&sKkT[d][j0 + 2];
            ull QK0 = *(const ull*)&sQkT[d][j0];
            ull QK1 = *(const ull*)&sQkT[d][j0 + 2];
            #pragma unroll
            for (int r = 0; r < 4; r++) {
                FMA2(acc1[r][0], Ap[r],  B0);
                FMA2(acc1[r][1], Ap[r],  B1);
                FMA2(acc2[r][0], KEp[r], QK0);
                FMA2(acc2[r][1], KEp[r], QK1);
            }
        }

        int soff = s0 - sb;
        #pragma unroll
        for (int r = 0; r < 4; r++) {
            int t = t0 + i0 + r;
            float a1v[4], a2v[4];
            UNPACK2(a1v[0], a1v[1], acc1[r][0]);
            UNPACK2(a1v[2], a1v[3], acc1[r][1]);
            UNPACK2(a2v[0], a2v[1], acc2[r][0]);
            UNPACK2(a2v[2], a2v[3], acc2[r][1]);
            #pragma unroll
            for (int c = 0; c < 4; c++) {
                int s = s0 + j0 + c;
                float v;
                if (s <= t && (t - s) <= 512)
                    v = (wstd * a1v[c] + wrec * a2v[c]) * 0.125f + wdisc * sd[soff + j0 + c];
                else
                    v = -1e30f;
                sL[(i0 + r) * LW + soff + j0 + c] = v;
            }
        }
    }
    __syncthreads();

    // ---- phase 2a: per-row max + exp (in place) + sum; 4 threads per row ----
    {
        int row = tid >> 2, l4 = tid & 3;
        float* rp = sL + row * LW;
        float m = -1e30f;
        for (int c = l4; c < L; c += 4) m = fmaxf(m, rp[c]);
        m = fmaxf(m, __shfl_xor_sync(0xffffffffu, m, 1));
        m = fmaxf(m, __shfl_xor_sync(0xffffffffu, m, 2));
        float s = 0.f;
        for (int c = l4; c < L; c += 4) {
            float ev = __expf(rp[c] - m);
            rp[c] = ev;
            s += ev;
        }
        s += __shfl_xor_sync(0xffffffffu, s, 1);
        s += __shfl_xor_sync(0xffffffffu, s, 2);
        if (l4 == 0) rowS[row] = 1.0f / s;
    }
    __syncthreads();

    // ---- phase 2b: write normalized attn band to gmem ----
    {
        size_t base = (size_t)h * TT * TT + (size_t)t0 * TT + sb;
        for (int i = 0; i < 64; i++) {
            float invs = rowS[i];
            const float* rp = sL + i * LW;
            float* op = attn_out + base + (size_t)i * TT;
            for (int c = tid; c < L; c += 256)
                op[c] = rp[c] * invs;
        }
    }

    // ---- phase 3: ctx = (exp) @ V, scaled by 1/rowsum at the end ----
    ull acc[4][2];
    #pragma unroll
    for (int r = 0; r < 4; r++) { acc[r][0] = 0ULL; acc[r][1] = 0ULL; }

    float (*sV)[66] = sKkT;   // reuse, now row-major [row][col]

    for (int kt = kt_lo; kt <= kt_hi; kt++) {
        int s0 = kt * 64;
        __syncthreads();
        for (int i = tid; i < 64 * 16; i += 256) {
            int row = i >> 4;
            int c4 = (i & 15) * 4;
            float4 v = *(const float4*)(g_V + (size_t)(s0 + row) * 768 + h * 64 + c4);
            sV[row][c4 + 0] = v.x; sV[row][c4 + 1] = v.y; sV[row][c4 + 2] = v.z; sV[row][c4 + 3] = v.w;
        }
        __syncthreads();
        int soff = s0 - sb;
        #pragma unroll 8
        for (int s = 0; s < 64; s++) {
            ull Pp[4];
            #pragma unroll
            for (int r = 0; r < 4; r++) PACK2(Pp[r], sL[(i0 + r) * LW + soff + s]);
            ull V0 = *(const ull*)&sV[s][j0];       // (66*s + j0) even -> aligned
            ull V1 = *(const ull*)&sV[s][j0 + 2];
            #pragma unroll
            for (int r = 0; r < 4; r++) {
                FMA2(acc[r][0], Pp[r], V0);
                FMA2(acc[r][1], Pp[r], V1);
            }
        }
    }

    #pragma unroll
    for (int r = 0; r < 4; r++) {
        float invs = rowS[i0 + r];
        float v0, v1, v2, v3;
        UNPACK2(v0, v1, acc[r][0]);
        UNPACK2(v2, v3, acc[r][1]);
        float* cp = g_ctx + (size_t)(t0 + i0 + r) * 768 + h * 64 + j0;
        cp[0] = v0 * invs; cp[1] = v1 * invs; cp[2] = v2 * invs; cp[3] = v3 * invs;
    }
}

// ---------------- launch ----------------------------------------------------
extern "C" void kernel_launch(void* const* d_in, const int* in_sizes, int n_in,
                              void* d_out, int out_size)
{
    const float* x     = (const float*)d_in[0];
    const float* Wq    = (const float*)d_in[1];
    const float* Wk    = (const float*)d_in[2];
    const float* Wv    = (const float*)d_in[3];
    const float* Wo    = (const float*)d_in[4];
    const float* gates = (const float*)d_in[5];
    const float* u     = (const float*)d_in[6];
    float* out  = (float*)d_out;
    float* attn = out + OUT_ELEMS;

    cudaFuncSetAttribute(attn_kernel, cudaFuncAttributeMaxDynamicSharedMemorySize, SMEM_BYTES);

    // QKV projections
    dim3 gq(12, 32, 3);
    sgemm_kernel<<<gq, 256>>>(x, Wq, Wk, Wv, nullptr, 0);

    // d bias from K
    dbias_kernel<<<12, 1024>>>(u);

    // banded gated attention (writes zeros + attn band + g_ctx; no memset needed)
    dim3 ga(64, 12, 1);
    attn_kernel<<<ga, 256, SMEM_BYTES>>>(gates, attn);

    // output projection
    dim3 go(12, 32, 1);
    sgemm_kernel<<<go, 256>>>(nullptr, Wo, nullptr, nullptr, out, 1);
}

// round 11
// speedup vs baseline: 1.2182x; 1.2182x over previous
#include <cuda_runtime.h>
#include <cuda_bf16.h>
#include <math.h>

#define TT 4096
#define EE 768
#define HH 12
#define DD 64
#define WIN 512
#define OUT_ELEMS (TT*EE)                 // 3145728
#define ATTN_ELEMS ((size_t)HH*TT*TT)     // 201326592

typedef unsigned long long ull;
typedef unsigned int u32;

// f32x2 packed-FMA helpers (attention kernel; neutral on pipe, saves issue)
#define PACK2(d, x)  asm("mov.b64 %0, {%1, %2};" : "=l"(d) : "f"(x), "f"(x))
#define FMA2(d, a, b) asm("fma.rn.f32x2 %0, %1, %2, %0;" : "+l"(d) : "l"(a), "l"(b))
#define UNPACK2(lo, hi, v) asm("mov.b64 {%0, %1}, %2;" : "=f"(lo), "=f"(hi) : "l"(v))

// ---------------- scratch (device globals: allocation-free) ----------------
__device__ __align__(16) float g_Q[TT*EE];
__device__ __align__(16) float g_K[TT*EE];
__device__ __align__(16) float g_V[TT*EE];
__device__ __align__(16) float g_d[HH*TT];

// bf16 two-term split buffers
__device__ __align__(16) __nv_bfloat16 g_xh[TT*EE], g_xl[TT*EE];
__device__ __align__(16) __nv_bfloat16 g_Wh[4][EE*EE], g_Wl[4][EE*EE];
__device__ __align__(16) __nv_bfloat16 g_ch[TT*EE], g_cl[TT*EE];   // ctx hi/lo

// ---------------- fp32 -> bf16 hi/lo split ----------------------------------
__global__ __launch_bounds__(256) void cvt_kernel(const float* __restrict__ src,
                                                  int dsel, int n4)
{
    int i = blockIdx.x * 256 + threadIdx.x;
    if (i >= n4) return;
    __nv_bfloat16 *hi, *lo;
    if (dsel == 0) { hi = g_xh; lo = g_xl; }
    else { hi = g_Wh[dsel - 1]; lo = g_Wl[dsel - 1]; }
    float4 v = ((const float4*)src)[i];
    __nv_bfloat16 h0 = __float2bfloat16_rn(v.x);
    __nv_bfloat16 h1 = __float2bfloat16_rn(v.y);
    __nv_bfloat16 h2 = __float2bfloat16_rn(v.z);
    __nv_bfloat16 h3 = __float2bfloat16_rn(v.w);
    __nv_bfloat16 l0 = __float2bfloat16_rn(v.x - __bfloat162float(h0));
    __nv_bfloat16 l1 = __float2bfloat16_rn(v.y - __bfloat162float(h1));
    __nv_bfloat16 l2 = __float2bfloat16_rn(v.z - __bfloat162float(h2));
    __nv_bfloat16 l3 = __float2bfloat16_rn(v.w - __bfloat162float(h3));
    uint2 hp, lp;
    hp.x = ((u32)__bfloat16_as_ushort(h1) << 16) | __bfloat16_as_ushort(h0);
    hp.y = ((u32)__bfloat16_as_ushort(h3) << 16) | __bfloat16_as_ushort(h2);
    lp.x = ((u32)__bfloat16_as_ushort(l1) << 16) | __bfloat16_as_ushort(l0);
    lp.y = ((u32)__bfloat16_as_ushort(l3) << 16) | __bfloat16_as_ushort(l2);
    ((uint2*)hi)[i] = hp;
    ((uint2*)lo)[i] = lp;
}

// ---------------- mma helpers ------------------------------------------------
__device__ __forceinline__ u32 smem_u32(const void* p) {
    return (u32)__cvta_generic_to_shared(p);
}
__device__ __forceinline__ void ldsm_x4(u32 addr, u32& r0, u32& r1, u32& r2, u32& r3) {
    asm volatile("ldmatrix.sync.aligned.m8n8.x4.shared.b16 {%0,%1,%2,%3}, [%4];"
        : "=r"(r0), "=r"(r1), "=r"(r2), "=r"(r3) : "r"(addr));
}
__device__ __forceinline__ void ldsm_x4t(u32 addr, u32& r0, u32& r1, u32& r2, u32& r3) {
    asm volatile("ldmatrix.sync.aligned.m8n8.x4.trans.shared.b16 {%0,%1,%2,%3}, [%4];"
        : "=r"(r0), "=r"(r1), "=r"(r2), "=r"(r3) : "r"(addr));
}
__device__ __forceinline__ void mma_bf16(float* d, const u32* a, u32 b0, u32 b1) {
    asm volatile(
        "mma.sync.aligned.m16n8k16.row.col.f32.bf16.bf16.f32 "
        "{%0,%1,%2,%3}, {%4,%5,%6,%7}, {%8,%9}, {%0,%1,%2,%3};"
        : "+f"(d[0]), "+f"(d[1]), "+f"(d[2]), "+f"(d[3])
        : "r"(a[0]), "r"(a[1]), "r"(a[2]), "r"(a[3]), "r"(b0), "r"(b1));
}

// ---------------- split-bf16 GEMM: C[4096,768] = A @ W[768,768] -------------
// BM=128, BN=64, BK=32; 8 warps in 4(M)x2(N); warp tile 32x32.
// 3 MMAs per fragment: Ah*Bh + Ah*Bl + Al*Bh  (error ~2^-16).
// wsel: 0/1/2 -> A=x_hi/lo, W=Wq/Wk/Wv, C=g_Q/g_K/g_V ; 3 -> A=ctx, W=Wo, C=Cext
#define LDA 40
#define LDB 72
__global__ __launch_bounds__(256) void bgemm_kernel(float* __restrict__ Cext, int wsel)
{
    const __nv_bfloat16 *Ah, *Al;
    const __nv_bfloat16 *Bh = g_Wh[wsel], *Bl = g_Wl[wsel];
    float* C;
    if (wsel < 3) {
        Ah = g_xh; Al = g_xl;
        C = (wsel == 0) ? g_Q : (wsel == 1) ? g_K : g_V;
    } else {
        Ah = g_ch; Al = g_cl; C = Cext;
    }

    __shared__ __nv_bfloat16 sAh[128][LDA], sAl[128][LDA];
    __shared__ __nv_bfloat16 sBh[32][LDB],  sBl[32][LDB];

    int tid = threadIdx.x;
    int wid = tid >> 5, lane = tid & 31;
    int m0 = blockIdx.y * 128, n0 = blockIdx.x * 64;
    int wm0 = (wid >> 1) * 32, wn0 = (wid & 1) * 32;
    int lr = lane & 15, lc = lane >> 4;

    float acc[2][4][4];
    #pragma unroll
    for (int mi = 0; mi < 2; mi++)
        #pragma unroll
        for (int nj = 0; nj < 4; nj++)
            #pragma unroll
            for (int q = 0; q < 4; q++) acc[mi][nj][q] = 0.f;

    for (int k0 = 0; k0 < 768; k0 += 32) {
        // A tile: 128x32 bf16 (hi+lo), 16B chunks: 512 chunks, 2/thread
        #pragma unroll
        for (int it = 0; it < 2; it++) {
            int idx = tid + it * 256;
            int row = idx >> 2;
            int kc = (idx & 3) * 8;
            *(uint4*)&sAh[row][kc] = *(const uint4*)(Ah + (size_t)(m0 + row) * 768 + k0 + kc);
            *(uint4*)&sAl[row][kc] = *(const uint4*)(Al + (size_t)(m0 + row) * 768 + k0 + kc);
        }
        // B tile: 32x64 bf16 (hi+lo): 256 chunks, 1/thread
        {
            int row = tid >> 3;
            int nc = (tid & 7) * 8;
            *(uint4*)&sBh[row][nc] = *(const uint4*)(Bh + (size_t)(k0 + row) * 768 + n0 + nc);
            *(uint4*)&sBl[row][nc] = *(const uint4*)(Bl + (size_t)(k0 + row) * 768 + n0 + nc);
        }
        __syncthreads();

        #pragma unroll
        for (int kk = 0; kk < 32; kk += 16) {
            u32 ah[2][4], al[2][4], bh[2][4], bl[2][4];
            #pragma unroll
            for (int mi = 0; mi < 2; mi++) {
                u32 adr = smem_u32(&sAh[wm0 + mi * 16 + lr][kk + lc * 8]);
                ldsm_x4(adr, ah[mi][0], ah[mi][1], ah[mi][2], ah[mi][3]);
                adr = smem_u32(&sAl[wm0 + mi * 16 + lr][kk + lc * 8]);
                ldsm_x4(adr, al[mi][0], al[mi][1], al[mi][2], al[mi][3]);
            }
            #pragma unroll
            for (int nj2 = 0; nj2 < 2; nj2++) {
                u32 adr = smem_u32(&sBh[kk + lr][wn0 + nj2 * 16 + lc * 8]);
                ldsm_x4t(adr, bh[nj2][0], bh[nj2][1], bh[nj2][2], bh[nj2][3]);
                adr = smem_u32(&sBl[kk + lr][wn0 + nj2 * 16 + lc * 8]);
                ldsm_x4t(adr, bl[nj2][0], bl[nj2][1], bl[nj2][2], bl[nj2][3]);
            }
            #pragma unroll
            for (int mi = 0; mi < 2; mi++)
                #pragma unroll
                for (int nj = 0; nj < 4; nj++) {
                    int j2 = nj >> 1, hf = (nj & 1) * 2;
                    mma_bf16(acc[mi][nj], ah[mi], bh[j2][hf], bh[j2][hf + 1]);
                    mma_bf16(acc[mi][nj], ah[mi], bl[j2][hf], bl[j2][hf + 1]);
                    mma_bf16(acc[mi][nj], al[mi], bh[j2][hf], bh[j2][hf + 1]);
                }
        }
        __syncthreads();
    }

    // epilogue
    int g = lane >> 2, t4 = lane & 3;
    #pragma unroll
    for (int mi = 0; mi < 2; mi++)
        #pragma unroll
        for (int nj = 0; nj < 4; nj++) {
            int row = m0 + wm0 + mi * 16 + g;
            int col = n0 + wn0 + nj * 8 + t4 * 2;
            float2 v0 = make_float2(acc[mi][nj][0], acc[mi][nj][1]);
            float2 v1 = make_float2(acc[mi][nj][2], acc[mi][nj][3]);
            *(float2*)&C[(size_t)row * 768 + col] = v0;
            *(float2*)&C[(size_t)(row + 8) * 768 + col] = v1;
        }
}

// ---------------- d bias: d[h,t] = K[t]·u[h] - mean_t(K[t]·u[h]) ------------
__global__ __launch_bounds__(1024) void dbias_kernel(const float* __restrict__ u)
{
    int h = blockIdx.x, tid = threadIdx.x;
    __shared__ float su[64];
    __shared__ float red[32];
    if (tid < 64) su[tid] = u[h * 64 + tid];
    __syncthreads();

    float vals[4];
    float lsum = 0.f;
    #pragma unroll
    for (int j = 0; j < 4; j++) {
        int t = j * 1024 + tid;
        const float4* kp = (const float4*)(g_K + (size_t)t * 768 + h * 64);
        float dot = 0.f;
        #pragma unroll
        for (int q = 0; q < 16; q++) {
            float4 kv = kp[q];
            dot += kv.x * su[q * 4] + kv.y * su[q * 4 + 1] + kv.z * su[q * 4 + 2] + kv.w * su[q * 4 + 3];
        }
        vals[j] = dot;
        lsum += dot;
    }
    #pragma unroll
    for (int o = 16; o > 0; o >>= 1) lsum += __shfl_xor_sync(0xffffffffu, lsum, o);
    if ((tid & 31) == 0) red[tid >> 5] = lsum;
    __syncthreads();
    if (tid < 32) {
        float v = red[tid];
        #pragma unroll
        for (int o = 16; o > 0; o >>= 1) v += __shfl_xor_sync(0xffffffffu, v, o);
        if (tid == 0) red[0] = v * (1.0f / 4096.0f);
    }
    __syncthreads();
    float mean = red[0];
    #pragma unroll
    for (int j = 0; j < 4; j++)
        g_d[h * 4096 + j * 1024 + tid] = vals[j] - mean;
}

// ---------------- attention: 64 query rows per block -----------------------
#define LW 577
#define SMEM_FLOATS (2*64*65 + 2*64*66 + 64*LW + 576 + 64)
#define SMEM_BYTES (SMEM_FLOATS * 4)

__global__ __launch_bounds__(256) void attn_kernel(
    const float* __restrict__ gates, float* __restrict__ attn_out)
{
    extern __shared__ float sm[];
    float (*sQq)[65] = (float(*)[65])sm;
    float (*sKq)[65] = sQq + 64;
    float (*sQkT)[66] = (float(*)[66])(sKq + 64);   // [d][col]
    float (*sKkT)[66] = sQkT + 64;                  // [d][col]; also V [row][col]
    float* sL = (float*)(sKkT + 64);      // 64 * 577
    float* sd = sL + 64 * LW;             // 576
    float* rowS = sd + 576;               // 64 (1/rowsum)

    int hh = blockIdx.y;
    int t0 = blockIdx.x * 64;
    int tid = threadIdx.x;
    int sb = t0 - 512; if (sb < 0) sb = 0;
    int L = t0 + 64 - sb;                 // multiple of 64, <= 576

    // ---- fused zero-fill of this block's out-of-band attn region ----
    {
        const float4 z4 = make_float4(0.f, 0.f, 0.f, 0.f);
        size_t rowbase = (size_t)hh * TT * TT + (size_t)t0 * TT;
        int leftq = sb >> 2;
        int right0 = t0 + 64;
        int rightq = (TT - right0) >> 2;
        for (int r = 0; r < 64; r++) {
            float4* bp = (float4*)(attn_out + rowbase + (size_t)r * TT);
            for (int c = tid; c < leftq; c += 256) bp[c] = z4;
            float4* rp4 = (float4*)(attn_out + rowbase + (size_t)r * TT + right0);
            for (int c = tid; c < rightq; c += 256) rp4[c] = z4;
        }
    }

    // gate softmax
    float g0 = gates[hh * 3 + 0], g1 = gates[hh * 3 + 1], g2 = gates[hh * 3 + 2];
    float gm = fmaxf(g0, fmaxf(g1, g2));
    float e0 = __expf(g0 - gm), e1 = __expf(g1 - gm), e2 = __expf(g2 - gm);
    float gi = 1.0f / (e0 + e1 + e2);
    float wstd = e0 * gi, wrec = e1 * gi, wdisc = e2 * gi;

    for (int i = tid; i < 64 * 16; i += 256) {
        int row = i >> 4;
        int c4 = (i & 15) * 4;
        float4 q = *(const float4*)(g_Q + (size_t)(t0 + row) * 768 + hh * 64 + c4);
        float4 k = *(const float4*)(g_K + (size_t)(t0 + row) * 768 + hh * 64 + c4);
        sQq[row][c4 + 0] = q.x; sQq[row][c4 + 1] = q.y; sQq[row][c4 + 2] = q.z; sQq[row][c4 + 3] = q.w;
        sKq[row][c4 + 0] = k.x; sKq[row][c4 + 1] = k.y; sKq[row][c4 + 2] = k.z; sKq[row][c4 + 3] = k.w;
    }
    for (int i = tid; i < L; i += 256) sd[i] = g_d[hh * 4096 + sb + i];

    int tx = tid & 15, ty = tid >> 4;
    int i0 = ty * 4, j0 = tx * 4;
    int kt_lo = sb >> 6, kt_hi = t0 >> 6;

    // ---- phase 1: banded logits into sL ----
    for (int kt = kt_lo; kt <= kt_hi; kt++) {
        int s0 = kt * 64;
        __syncthreads();
        for (int i = tid; i < 64 * 16; i += 256) {
            int row = i >> 4;
            int c4 = (i & 15) * 4;
            float4 q = *(const float4*)(g_Q + (size_t)(s0 + row) * 768 + hh * 64 + c4);
            float4 k = *(const float4*)(g_K + (size_t)(s0 + row) * 768 + hh * 64 + c4);
            sQkT[c4 + 0][row] = q.x; sQkT[c4 + 1][row] = q.y; sQkT[c4 + 2][row] = q.z; sQkT[c4 + 3][row] = q.w;
            sKkT[c4 + 0][row] = k.x; sKkT[c4 + 1][row] = k.y; sKkT[c4 + 2][row] = k.z; sKkT[c4 + 3][row] = k.w;
        }
        __syncthreads();

        ull acc1[4][2], acc2[4][2];
        #pragma unroll
        for (int r = 0; r < 4; r++) {
            acc1[r][0] = 0ULL; acc1[r][1] = 0ULL;
            acc2[r][0] = 0ULL; acc2[r][1] = 0ULL;
        }

        #pragma unroll 8
        for (int d = 0; d < 64; d++) {
            ull Ap[4], KEp[4];
            #pragma unroll
            for (int r = 0; r < 4; r++) {
                PACK2(Ap[r],  sQq[i0 + r][d]);
                PACK2(KEp[r], sKq[i0 + r][d]);
            }
            ull B0  = *(const ull*)&sKkT[d][j0];
            ull B1  = *(const ull*)&sKkT[d][j0 + 2];
            ull QK0 = *(const ull*)&sQkT[d][j0];
            ull QK1 = *(const ull*)&sQkT[d][j0 + 2];
            #pragma unroll
            for (int r = 0; r < 4; r++) {
                FMA2(acc1[r][0], Ap[r],  B0);
                FMA2(acc1[r][1], Ap[r],  B1);
                FMA2(acc2[r][0], KEp[r], QK0);
                FMA2(acc2[r][1], KEp[r], QK1);
            }
        }

        int soff = s0 - sb;
        #pragma unroll
        for (int r = 0; r < 4; r++) {
            int t = t0 + i0 + r;
            float a1v[4], a2v[4];
            UNPACK2(a1v[0], a1v[1], acc1[r][0]);
            UNPACK2(a1v[2], a1v[3], acc1[r][1]);
            UNPACK2(a2v[0], a2v[1], acc2[r][0]);
            UNPACK2(a2v[2], a2v[3], acc2[r][1]);
            #pragma unroll
            for (int c = 0; c < 4; c++) {
                int s = s0 + j0 + c;
                float v;
                if (s <= t && (t - s) <= 512)
                    v = (wstd * a1v[c] + wrec * a2v[c]) * 0.125f + wdisc * sd[soff + j0 + c];
                else
                    v = -1e30f;
                sL[(i0 + r) * LW + soff + j0 + c] = v;
            }
        }
    }
    __syncthreads();

    // ---- phase 2a: per-row max + exp + sum ----
    {
        int row = tid >> 2, l4 = tid & 3;
        float* rp = sL + row * LW;
        float m = -1e30f;
        for (int c = l4; c < L; c += 4) m = fmaxf(m, rp[c]);
        m = fmaxf(m, __shfl_xor_sync(0xffffffffu, m, 1));
        m = fmaxf(m, __shfl_xor_sync(0xffffffffu, m, 2));
        float s = 0.f;
        for (int c = l4; c < L; c += 4) {
            float ev = __expf(rp[c] - m);
            rp[c] = ev;
            s += ev;
        }
        s += __shfl_xor_sync(0xffffffffu, s, 1);
        s += __shfl_xor_sync(0xffffffffu, s, 2);
        if (l4 == 0) rowS[row] = 1.0f / s;
    }
    __syncthreads();

    // ---- phase 2b: write normalized attn band to gmem ----
    {
        size_t base = (size_t)hh * TT * TT + (size_t)t0 * TT + sb;
        for (int i = 0; i < 64; i++) {
            float invs = rowS[i];
            const float* rp = sL + i * LW;
            float* op = attn_out + base + (size_t)i * TT;
            for (int c = tid; c < L; c += 256)
                op[c] = rp[c] * invs;
        }
    }

    // ---- phase 3: ctx = (exp) @ V, scaled, written as bf16 hi/lo ----
    ull acc[4][2];
    #pragma unroll
    for (int r = 0; r < 4; r++) { acc[r][0] = 0ULL; acc[r][1] = 0ULL; }

    float (*sV)[66] = sKkT;

    for (int kt = kt_lo; kt <= kt_hi; kt++) {
        int s0 = kt * 64;
        __syncthreads();
        for (int i = tid; i < 64 * 16; i += 256) {
            int row = i >> 4;
            int c4 = (i & 15) * 4;
            float4 v = *(const float4*)(g_V + (size_t)(s0 + row) * 768 + hh * 64 + c4);
            sV[row][c4 + 0] = v.x; sV[row][c4 + 1] = v.y; sV[row][c4 + 2] = v.z; sV[row][c4 + 3] = v.w;
        }
        __syncthreads();
        int soff = s0 - sb;
        #pragma unroll 8
        for (int s = 0; s < 64; s++) {
            ull Pp[4];
            #pragma unroll
            for (int r = 0; r < 4; r++) PACK2(Pp[r], sL[(i0 + r) * LW + soff + s]);
            ull V0 = *(const ull*)&sV[s][j0];
            ull V1 = *(const ull*)&sV[s][j0 + 2];
            #pragma unroll
            for (int r = 0; r < 4; r++) {
                FMA2(acc[r][0], Pp[r], V0);
                FMA2(acc[r][1], Pp[r], V1);
            }
        }
    }

    #pragma unroll
    for (int r = 0; r < 4; r++) {
        float invs = rowS[i0 + r];
        float v0, v1, v2, v3;
        UNPACK2(v0, v1, acc[r][0]);
        UNPACK2(v2, v3, acc[r][1]);
        v0 *= invs; v1 *= invs; v2 *= invs; v3 *= invs;
        __nv_bfloat16 h0 = __float2bfloat16_rn(v0);
        __nv_bfloat16 h1 = __float2bfloat16_rn(v1);
        __nv_bfloat16 h2 = __float2bfloat16_rn(v2);
        __nv_bfloat16 h3 = __float2bfloat16_rn(v3);
        __nv_bfloat16 l0 = __float2bfloat16_rn(v0 - __bfloat162float(h0));
        __nv_bfloat16 l1 = __float2bfloat16_rn(v1 - __bfloat162float(h1));
        __nv_bfloat16 l2 = __float2bfloat16_rn(v2 - __bfloat162float(h2));
        __nv_bfloat16 l3 = __float2bfloat16_rn(v3 - __bfloat162float(h3));
        uint2 hp, lp;
        hp.x = ((u32)__bfloat16_as_ushort(h1) << 16) | __bfloat16_as_ushort(h0);
        hp.y = ((u32)__bfloat16_as_ushort(h3) << 16) | __bfloat16_as_ushort(h2);
        lp.x = ((u32)__bfloat16_as_ushort(l1) << 16) | __bfloat16_as_ushort(l0);
        lp.y = ((u32)__bfloat16_as_ushort(l3) << 16) | __bfloat16_as_ushort(l2);
        size_t off = (size_t)(t0 + i0 + r) * 768 + hh * 64 + j0;
        *(uint2*)(g_ch + off) = hp;
        *(uint2*)(g_cl + off) = lp;
    }
}

// ---------------- launch ----------------------------------------------------
extern "C" void kernel_launch(void* const* d_in, const int* in_sizes, int n_in,
                              void* d_out, int out_size)
{
    const float* x     = (const float*)d_in[0];
    const float* Wq    = (const float*)d_in[1];
    const float* Wk    = (const float*)d_in[2];
    const float* Wv    = (const float*)d_in[3];
    const float* Wo    = (const float*)d_in[4];
    const float* gates = (const float*)d_in[5];
    const float* u     = (const float*)d_in[6];
    float* out  = (float*)d_out;
    float* attn = out + OUT_ELEMS;

    cudaFuncSetAttribute(attn_kernel, cudaFuncAttributeMaxDynamicSharedMemorySize, SMEM_BYTES);

    // split fp32 -> bf16 hi/lo
    cvt_kernel<<<(OUT_ELEMS/4 + 255)/256, 256>>>(x,  0, OUT_ELEMS/4);
    cvt_kernel<<<(EE*EE/4  + 255)/256, 256>>>(Wq, 1, EE*EE/4);
    cvt_kernel<<<(EE*EE/4  + 255)/256, 256>>>(Wk, 2, EE*EE/4);
    cvt_kernel<<<(EE*EE/4  + 255)/256, 256>>>(Wv, 3, EE*EE/4);
    cvt_kernel<<<(EE*EE/4  + 255)/256, 256>>>(Wo, 4, EE*EE/4);

    // QKV projections (tensor-core split-bf16)
    dim3 gb(12, 32);
    bgemm_kernel<<<gb, 256>>>(nullptr, 0);
    bgemm_kernel<<<gb, 256>>>(nullptr, 1);
    bgemm_kernel<<<gb, 256>>>(nullptr, 2);

    // d bias from K
    dbias_kernel<<<12, 1024>>>(u);

    // banded gated attention (zero-fill + attn band + ctx hi/lo)
    dim3 ga(64, 12, 1);
    attn_kernel<<<ga, 256, SMEM_BYTES>>>(gates, attn);

    // output projection
    bgemm_kernel<<<gb, 256>>>(out, 3);
}

// round 12
// speedup vs baseline: 1.6462x; 1.3513x over previous
#include <cuda_runtime.h>
#include <cuda_bf16.h>
#include <math.h>

#define TT 4096
#define EE 768
#define HH 12
#define DD 64
#define WIN 512
#define OUT_ELEMS (TT*EE)                 // 3145728
#define ATTN_ELEMS ((size_t)HH*TT*TT)     // 201326592

typedef unsigned long long ull;
typedef unsigned int u32;

// ---------------- scratch (device globals: allocation-free) ----------------
__device__ __align__(16) float g_d[HH*TT];

// bf16 two-term split buffers
__device__ __align__(16) __nv_bfloat16 g_xh[TT*EE], g_xl[TT*EE];
__device__ __align__(16) __nv_bfloat16 g_Wh[4][EE*EE], g_Wl[4][EE*EE];
__device__ __align__(16) __nv_bfloat16 g_Qh[TT*EE], g_Ql[TT*EE];
__device__ __align__(16) __nv_bfloat16 g_Kh[TT*EE], g_Kl[TT*EE];
__device__ __align__(16) __nv_bfloat16 g_Vh[TT*EE], g_Vl[TT*EE];
__device__ __align__(16) __nv_bfloat16 g_ch[TT*EE], g_cl[TT*EE];   // ctx hi/lo

// ---------------- helpers ----------------------------------------------------
__device__ __forceinline__ u32 pack_bf16x2(float a, float b) {
    __nv_bfloat16 ha = __float2bfloat16_rn(a), hb = __float2bfloat16_rn(b);
    return ((u32)__bfloat16_as_ushort(hb) << 16) | __bfloat16_as_ushort(ha);
}
// fast exp on FMA pipe: exp(x) = 2^(x*log2e), poly deg-5, ~2e-7 rel err
__device__ __forceinline__ float fast_exp(float x) {
    float y = fmaxf(x * 1.4426950408889634f, -126.0f);
    float n = floorf(y);
    float f = y - n;
    float p = 1.8775767e-3f;
    p = fmaf(p, f, 8.9893397e-3f);
    p = fmaf(p, f, 5.5826318e-2f);
    p = fmaf(p, f, 2.4015361e-1f);
    p = fmaf(p, f, 6.9315308e-1f);
    p = fmaf(p, f, 1.0f);
    float s = __int_as_float(((int)n + 127) << 23);
    return p * s;
}

// ---------------- fp32 -> bf16 hi/lo split ----------------------------------
__global__ __launch_bounds__(256) void cvt_kernel(const float* __restrict__ src,
                                                  int dsel, int n4)
{
    int i = blockIdx.x * 256 + threadIdx.x;
    if (i >= n4) return;
    __nv_bfloat16 *hi, *lo;
    if (dsel == 0) { hi = g_xh; lo = g_xl; }
    else { hi = g_Wh[dsel - 1]; lo = g_Wl[dsel - 1]; }
    float4 v = ((const float4*)src)[i];
    float h0f = __bfloat162float(__float2bfloat16_rn(v.x));
    float h1f = __bfloat162float(__float2bfloat16_rn(v.y));
    float h2f = __bfloat162float(__float2bfloat16_rn(v.z));
    float h3f = __bfloat162float(__float2bfloat16_rn(v.w));
    uint2 hp, lp;
    hp.x = pack_bf16x2(v.x, v.y);
    hp.y = pack_bf16x2(v.z, v.w);
    lp.x = pack_bf16x2(v.x - h0f, v.y - h1f);
    lp.y = pack_bf16x2(v.z - h2f, v.w - h3f);
    ((uint2*)hi)[i] = hp;
    ((uint2*)lo)[i] = lp;
}

// ---------------- mma helpers ------------------------------------------------
__device__ __forceinline__ u32 smem_u32(const void* p) {
    return (u32)__cvta_generic_to_shared(p);
}
__device__ __forceinline__ void ldsm_x4(u32 addr, u32& r0, u32& r1, u32& r2, u32& r3) {
    asm volatile("ldmatrix.sync.aligned.m8n8.x4.shared.b16 {%0,%1,%2,%3}, [%4];"
        : "=r"(r0), "=r"(r1), "=r"(r2), "=r"(r3) : "r"(addr));
}
__device__ __forceinline__ void ldsm_x4t(u32 addr, u32& r0, u32& r1, u32& r2, u32& r3) {
    asm volatile("ldmatrix.sync.aligned.m8n8.x4.trans.shared.b16 {%0,%1,%2,%3}, [%4];"
        : "=r"(r0), "=r"(r1), "=r"(r2), "=r"(r3) : "r"(addr));
}
__device__ __forceinline__ void mma_bf16(float* d, const u32* a, u32 b0, u32 b1) {
    asm volatile(
        "mma.sync.aligned.m16n8k16.row.col.f32.bf16.bf16.f32 "
        "{%0,%1,%2,%3}, {%4,%5,%6,%7}, {%8,%9}, {%0,%1,%2,%3};"
        : "+f"(d[0]), "+f"(d[1]), "+f"(d[2]), "+f"(d[3])
        : "r"(a[0]), "r"(a[1]), "r"(a[2]), "r"(a[3]), "r"(b0), "r"(b1));
}

// ---------------- split-bf16 GEMM: C[4096,768] = A @ W[768,768] -------------
// wsel 0/1/2: A=x, W=Wq/Wk/Wv, C -> g_{Q,K,V}{h,l} (bf16 hi/lo)
// wsel 3:     A=ctx(hi/lo),  W=Wo,       C -> Cext (fp32)
#define LDA 40
#define LDB 72
__global__ __launch_bounds__(256) void bgemm_kernel(float* __restrict__ Cext, int wsel)
{
    const __nv_bfloat16 *Ah, *Al;
    const __nv_bfloat16 *Bh = g_Wh[wsel], *Bl = g_Wl[wsel];
    __nv_bfloat16 *Ch = nullptr, *Cl = nullptr;
    if (wsel < 3) {
        Ah = g_xh; Al = g_xl;
        Ch = (wsel == 0) ? g_Qh : (wsel == 1) ? g_Kh : g_Vh;
        Cl = (wsel == 0) ? g_Ql : (wsel == 1) ? g_Kl : g_Vl;
    } else {
        Ah = g_ch; Al = g_cl;
    }

    __shared__ __nv_bfloat16 sAh[128][LDA], sAl[128][LDA];
    __shared__ __nv_bfloat16 sBh[32][LDB],  sBl[32][LDB];

    int tid = threadIdx.x;
    int wid = tid >> 5, lane = tid & 31;
    int m0 = blockIdx.y * 128, n0 = blockIdx.x * 64;
    int wm0 = (wid >> 1) * 32, wn0 = (wid & 1) * 32;
    int lr = lane & 15, lc = lane >> 4;

    float acc[2][4][4];
    #pragma unroll
    for (int mi = 0; mi < 2; mi++)
        #pragma unroll
        for (int nj = 0; nj < 4; nj++)
            #pragma unroll
            for (int q = 0; q < 4; q++) acc[mi][nj][q] = 0.f;

    for (int k0 = 0; k0 < 768; k0 += 32) {
        #pragma unroll
        for (int it = 0; it < 2; it++) {
            int idx = tid + it * 256;
            int row = idx >> 2;
            int kc = (idx & 3) * 8;
            *(uint4*)&sAh[row][kc] = *(const uint4*)(Ah + (size_t)(m0 + row) * 768 + k0 + kc);
            *(uint4*)&sAl[row][kc] = *(const uint4*)(Al + (size_t)(m0 + row) * 768 + k0 + kc);
        }
        {
            int row = tid >> 3;
            int nc = (tid & 7) * 8;
            *(uint4*)&sBh[row][nc] = *(const uint4*)(Bh + (size_t)(k0 + row) * 768 + n0 + nc);
            *(uint4*)&sBl[row][nc] = *(const uint4*)(Bl + (size_t)(k0 + row) * 768 + n0 + nc);
        }
        __syncthreads();

        #pragma unroll
        for (int kk = 0; kk < 32; kk += 16) {
            u32 ah[2][4], al[2][4], bh[2][4], bl[2][4];
            #pragma unroll
            for (int mi = 0; mi < 2; mi++) {
                u32 adr = smem_u32(&sAh[wm0 + mi * 16 + lr][kk + lc * 8]);
                ldsm_x4(adr, ah[mi][0], ah[mi][1], ah[mi][2], ah[mi][3]);
                adr = smem_u32(&sAl[wm0 + mi * 16 + lr][kk + lc * 8]);
                ldsm_x4(adr, al[mi][0], al[mi][1], al[mi][2], al[mi][3]);
            }
            #pragma unroll
            for (int nj2 = 0; nj2 < 2; nj2++) {
                u32 adr = smem_u32(&sBh[kk + lr][wn0 + nj2 * 16 + lc * 8]);
                ldsm_x4t(adr, bh[nj2][0], bh[nj2][1], bh[nj2][2], bh[nj2][3]);
                adr = smem_u32(&sBl[kk + lr][wn0 + nj2 * 16 + lc * 8]);
                ldsm_x4t(adr, bl[nj2][0], bl[nj2][1], bl[nj2][2], bl[nj2][3]);
            }
            #pragma unroll
            for (int mi = 0; mi < 2; mi++)
                #pragma unroll
                for (int nj = 0; nj < 4; nj++) {
                    int j2 = nj >> 1, hf = (nj & 1) * 2;
                    mma_bf16(acc[mi][nj], ah[mi], bh[j2][hf], bh[j2][hf + 1]);
                    mma_bf16(acc[mi][nj], ah[mi], bl[j2][hf], bl[j2][hf + 1]);
                    mma_bf16(acc[mi][nj], al[mi], bh[j2][hf], bh[j2][hf + 1]);
                }
        }
        __syncthreads();
    }

    int g = lane >> 2, t4 = lane & 3;
    #pragma unroll
    for (int mi = 0; mi < 2; mi++)
        #pragma unroll
        for (int nj = 0; nj < 4; nj++) {
            int row = m0 + wm0 + mi * 16 + g;
            int col = n0 + wn0 + nj * 8 + t4 * 2;
            if (wsel == 3) {
                *(float2*)&Cext[(size_t)row * 768 + col] =
                    make_float2(acc[mi][nj][0], acc[mi][nj][1]);
                *(float2*)&Cext[(size_t)(row + 8) * 768 + col] =
                    make_float2(acc[mi][nj][2], acc[mi][nj][3]);
            } else {
                #pragma unroll
                for (int rr = 0; rr < 2; rr++) {
                    float v0 = acc[mi][nj][rr * 2], v1 = acc[mi][nj][rr * 2 + 1];
                    float h0 = __bfloat162float(__float2bfloat16_rn(v0));
                    float h1 = __bfloat162float(__float2bfloat16_rn(v1));
                    size_t off = (size_t)(row + rr * 8) * 768 + col;
                    *(u32*)(Ch + off) = pack_bf16x2(v0, v1);
                    *(u32*)(Cl + off) = pack_bf16x2(v0 - h0, v1 - h1);
                }
            }
        }
}

// ---------------- d bias: d[h,t] = K[t]·u[h] - mean_t ------------------------
__global__ __launch_bounds__(1024) void dbias_kernel(const float* __restrict__ u)
{
    int h = blockIdx.x, tid = threadIdx.x;
    __shared__ float su[64];
    __shared__ float red[32];
    if (tid < 64) su[tid] = u[h * 64 + tid];
    __syncthreads();

    float vals[4];
    float lsum = 0.f;
    #pragma unroll
    for (int j = 0; j < 4; j++) {
        int t = j * 1024 + tid;
        const __nv_bfloat162* kh = (const __nv_bfloat162*)(g_Kh + (size_t)t * 768 + h * 64);
        const __nv_bfloat162* kl = (const __nv_bfloat162*)(g_Kl + (size_t)t * 768 + h * 64);
        float dot = 0.f;
        #pragma unroll
        for (int q = 0; q < 32; q++) {
            float2 hv = __bfloat1622float2(kh[q]);
            float2 lv = __bfloat1622float2(kl[q]);
            dot += (hv.x + lv.x) * su[q * 2] + (hv.y + lv.y) * su[q * 2 + 1];
        }
        vals[j] = dot;
        lsum += dot;
    }
    #pragma unroll
    for (int o = 16; o > 0; o >>= 1) lsum += __shfl_xor_sync(0xffffffffu, lsum, o);
    if ((tid & 31) == 0) red[tid >> 5] = lsum;
    __syncthreads();
    if (tid < 32) {
        float v = red[tid];
        #pragma unroll
        for (int o = 16; o > 0; o >>= 1) v += __shfl_xor_sync(0xffffffffu, v, o);
        if (tid == 0) red[0] = v * (1.0f / 4096.0f);
    }
    __syncthreads();
    float mean = red[0];
    #pragma unroll
    for (int j = 0; j < 4; j++)
        g_d[h * 4096 + j * 1024 + tid] = vals[j] - mean;
}

// ---------------- attention: 64 query rows per block, tensor-core ----------
// smem: sL fp32 [64][577]; bf16 tiles [64][72]: Qh,Ql,Kqh,Kql (query rows,
// reused as Ph,Pl in phase 3) + Kbh,Kbl,Qbh,Qbl (key block, reused as Vh,Vl).
#define LW 577
#define TLD 72
#define SMEM_BYTES (64*LW*4 + 8*64*TLD*2 + 576*4 + 64*4)

__global__ __launch_bounds__(256) void attn_kernel(
    const float* __restrict__ gates, float* __restrict__ attn_out)
{
    extern __shared__ char smraw[];
    float* sL = (float*)smraw;                                  // 64*577 f32
    __nv_bfloat16 (*sQh)[TLD]  = (__nv_bfloat16(*)[TLD])(smraw + 64*LW*4);
    __nv_bfloat16 (*sQl)[TLD]  = sQh  + 64;
    __nv_bfloat16 (*sKqh)[TLD] = sQl  + 64;
    __nv_bfloat16 (*sKql)[TLD] = sKqh + 64;
    __nv_bfloat16 (*sKbh)[TLD] = sKql + 64;
    __nv_bfloat16 (*sKbl)[TLD] = sKbh + 64;
    __nv_bfloat16 (*sQbh)[TLD] = sKbl + 64;
    __nv_bfloat16 (*sQbl)[TLD] = sQbh + 64;
    float* sd   = (float*)(sQbl + 64);                          // 576
    float* rowS = sd + 576;                                     // 64

    // phase-3 aliases
    __nv_bfloat16 (*sPh)[TLD] = sQh,  (*sPl)[TLD] = sQl;
    __nv_bfloat16 (*sVh)[TLD] = sKbh, (*sVl)[TLD] = sKbl;

    int hh = blockIdx.y;
    int t0 = blockIdx.x * 64;
    int tid = threadIdx.x;
    int wid = tid >> 5, lane = tid & 31;
    int sb = t0 - 512; if (sb < 0) sb = 0;
    int L = t0 + 64 - sb;

    // ---- fused zero-fill of out-of-band attn region (fire-and-forget) ----
    {
        const float4 z4 = make_float4(0.f, 0.f, 0.f, 0.f);
        size_t rowbase = (size_t)hh * TT * TT + (size_t)t0 * TT;
        int leftq = sb >> 2;
        int right0 = t0 + 64;
        int rightq = (TT - right0) >> 2;
        for (int r = 0; r < 64; r++) {
            float4* bp = (float4*)(attn_out + rowbase + (size_t)r * TT);
            for (int c = tid; c < leftq; c += 256) bp[c] = z4;
            float4* rp4 = (float4*)(attn_out + rowbase + (size_t)r * TT + right0);
            for (int c = tid; c < rightq; c += 256) rp4[c] = z4;
        }
    }

    // gate softmax
    float g0 = gates[hh * 3 + 0], g1 = gates[hh * 3 + 1], g2 = gates[hh * 3 + 2];
    float gm = fmaxf(g0, fmaxf(g1, g2));
    float e0 = fast_exp(g0 - gm), e1 = fast_exp(g1 - gm), e2 = fast_exp(g2 - gm);
    float gi = 1.0f / (e0 + e1 + e2);
    float wstd = e0 * gi, wrec = e1 * gi, wdisc = e2 * gi;

    // load query-row tiles (Q,K hi/lo) + d band
    for (int i = tid; i < 64 * 8; i += 256) {
        int row = i >> 3;
        int c8 = (i & 7) * 8;
        size_t off = (size_t)(t0 + row) * 768 + hh * 64 + c8;
        *(uint4*)&sQh[row][c8]  = *(const uint4*)(g_Qh + off);
        *(uint4*)&sQl[row][c8]  = *(const uint4*)(g_Ql + off);
        *(uint4*)&sKqh[row][c8] = *(const uint4*)(g_Kh + off);
        *(uint4*)&sKql[row][c8] = *(const uint4*)(g_Kl + off);
    }
    for (int i = tid; i < L; i += 256) sd[i] = g_d[hh * 4096 + sb + i];

    int wm0 = (wid >> 1) * 16, wn0 = (wid & 1) * 32;
    int lr = lane & 15, lc = lane >> 4;
    int g = lane >> 2, t4 = lane & 3;
    int kt_lo = sb >> 6, kt_hi = t0 >> 6;

    // ---- phase 1: banded logits via split-bf16 MMA ----
    for (int kt = kt_lo; kt <= kt_hi; kt++) {
        int s0 = kt * 64;
        __syncthreads();
        for (int i = tid; i < 64 * 8; i += 256) {
            int row = i >> 3;
            int c8 = (i & 7) * 8;
            size_t off = (size_t)(s0 + row) * 768 + hh * 64 + c8;
            *(uint4*)&sKbh[row][c8] = *(const uint4*)(g_Kh + off);
            *(uint4*)&sKbl[row][c8] = *(const uint4*)(g_Kl + off);
            *(uint4*)&sQbh[row][c8] = *(const uint4*)(g_Qh + off);
            *(uint4*)&sQbl[row][c8] = *(const uint4*)(g_Ql + off);
        }
        __syncthreads();

        float acc1[4][4], acc2[4][4];
        #pragma unroll
        for (int nj = 0; nj < 4; nj++)
            #pragma unroll
            for (int q = 0; q < 4; q++) { acc1[nj][q] = 0.f; acc2[nj][q] = 0.f; }

        #pragma unroll
        for (int kk = 0; kk < 64; kk += 16) {
            u32 aqh[4], aql[4], akh[4], akl[4];
            u32 adr = smem_u32(&sQh[wm0 + lr][kk + lc * 8]);
            ldsm_x4(adr, aqh[0], aqh[1], aqh[2], aqh[3]);
            adr = smem_u32(&sQl[wm0 + lr][kk + lc * 8]);
            ldsm_x4(adr, aql[0], aql[1], aql[2], aql[3]);
            adr = smem_u32(&sKqh[wm0 + lr][kk + lc * 8]);
            ldsm_x4(adr, akh[0], akh[1], akh[2], akh[3]);
            adr = smem_u32(&sKql[wm0 + lr][kk + lc * 8]);
            ldsm_x4(adr, akl[0], akl[1], akl[2], akl[3]);

            u32 bkh[2][4], bkl[2][4], bqh[2][4], bql[2][4];
            #pragma unroll
            for (int nj2 = 0; nj2 < 2; nj2++) {
                adr = smem_u32(&sKbh[wn0 + nj2 * 16 + lr][kk + lc * 8]);
                ldsm_x4(adr, bkh[nj2][0], bkh[nj2][1], bkh[nj2][2], bkh[nj2][3]);
                adr = smem_u32(&sKbl[wn0 + nj2 * 16 + lr][kk + lc * 8]);
                ldsm_x4(adr, bkl[nj2][0], bkl[nj2][1], bkl[nj2][2], bkl[nj2][3]);
                adr = smem_u32(&sQbh[wn0 + nj2 * 16 + lr][kk + lc * 8]);
                ldsm_x4(adr, bqh[nj2][0], bqh[nj2][1], bqh[nj2][2], bqh[nj2][3]);
                adr = smem_u32(&sQbl[wn0 + nj2 * 16 + lr][kk + lc * 8]);
                ldsm_x4(adr, bql[nj2][0], bql[nj2][1], bql[nj2][2], bql[nj2][3]);
            }
            // non-trans [n][k] ldsm: n-half nh uses regs {r[nh], r[nh+2]}
            #pragma unroll
            for (int nj = 0; nj < 4; nj++) {
                int j2 = nj >> 1, nh = nj & 1;
                mma_bf16(acc1[nj], aqh, bkh[j2][nh], bkh[j2][nh + 2]);
                mma_bf16(acc1[nj], aqh, bkl[j2][nh], bkl[j2][nh + 2]);
                mma_bf16(acc1[nj], aql, bkh[j2][nh], bkh[j2][nh + 2]);
                mma_bf16(acc2[nj], akh, bqh[j2][nh], bqh[j2][nh + 2]);
                mma_bf16(acc2[nj], akh, bql[j2][nh], bql[j2][nh + 2]);
                mma_bf16(acc2[nj], akl, bqh[j2][nh], bqh[j2][nh + 2]);
            }
        }

        int soff = s0 - sb;
        #pragma unroll
        for (int nj = 0; nj < 4; nj++)
            #pragma unroll
            for (int q = 0; q < 4; q++) {
                int rl = wm0 + g + (q >> 1) * 8;
                int cl = wn0 + nj * 8 + t4 * 2 + (q & 1);
                int t = t0 + rl, s = s0 + cl;
                float v;
                if (s <= t && (t - s) <= 512)
                    v = (wstd * acc1[nj][q] + wrec * acc2[nj][q]) * 0.125f + wdisc * sd[soff + cl];
                else
                    v = -1e30f;
                sL[rl * LW + soff + cl] = v;
            }
    }
    __syncthreads();

    // ---- phase 2a: per-row max + exp (in place) + sum; 4 threads/row ----
    {
        int row = tid >> 2, l4 = tid & 3;
        float* rp = sL + row * LW;
        float m = -1e30f;
        for (int c = l4; c < L; c += 4) m = fmaxf(m, rp[c]);
        m = fmaxf(m, __shfl_xor_sync(0xffffffffu, m, 1));
        m = fmaxf(m, __shfl_xor_sync(0xffffffffu, m, 2));
        float s = 0.f;
        for (int c = l4; c < L; c += 4) {
            float ev = fast_exp(rp[c] - m);
            rp[c] = ev;
            s += ev;
        }
        s += __shfl_xor_sync(0xffffffffu, s, 1);
        s += __shfl_xor_sync(0xffffffffu, s, 2);
        if (l4 == 0) rowS[row] = 1.0f / s;
    }
    __syncthreads();

    // ---- phase 2b: write normalized attn band ----
    {
        size_t base = (size_t)hh * TT * TT + (size_t)t0 * TT + sb;
        for (int i = 0; i < 64; i++) {
            float invs = rowS[i];
            const float* rp = sL + i * LW;
            float* op = attn_out + base + (size_t)i * TT;
            for (int c = tid; c < L; c += 256)
                op[c] = rp[c] * invs;
        }
    }

    // ---- phase 3: ctx = P @ V via split-bf16 MMA ----
    float acc3[4][4];
    #pragma unroll
    for (int nj = 0; nj < 4; nj++)
        #pragma unroll
        for (int q = 0; q < 4; q++) acc3[nj][q] = 0.f;

    for (int kt = kt_lo; kt <= kt_hi; kt++) {
        int s0 = kt * 64;
        int soff = s0 - sb;
        __syncthreads();
        // stage P block (exp values) as bf16 hi/lo; load V block hi/lo
        for (int i = tid; i < 64 * 32; i += 256) {
            int row = i >> 5;
            int c2 = (i & 31) * 2;
            float v0 = sL[row * LW + soff + c2];
            float v1 = sL[row * LW + soff + c2 + 1];
            float h0 = __bfloat162float(__float2bfloat16_rn(v0));
            float h1 = __bfloat162float(__float2bfloat16_rn(v1));
            *(u32*)&sPh[row][c2] = pack_bf16x2(v0, v1);
            *(u32*)&sPl[row][c2] = pack_bf16x2(v0 - h0, v1 - h1);
        }
        for (int i = tid; i < 64 * 8; i += 256) {
            int row = i >> 3;
            int c8 = (i & 7) * 8;
            size_t off = (size_t)(s0 + row) * 768 + hh * 64 + c8;
            *(uint4*)&sVh[row][c8] = *(const uint4*)(g_Vh + off);
            *(uint4*)&sVl[row][c8] = *(const uint4*)(g_Vl + off);
        }
        __syncthreads();

        #pragma unroll
        for (int kk = 0; kk < 64; kk += 16) {
            u32 aph[4], apl[4];
            u32 adr = smem_u32(&sPh[wm0 + lr][kk + lc * 8]);
            ldsm_x4(adr, aph[0], aph[1], aph[2], aph[3]);
            adr = smem_u32(&sPl[wm0 + lr][kk + lc * 8]);
            ldsm_x4(adr, apl[0], apl[1], apl[2], apl[3]);
            u32 bvh[2][4], bvl[2][4];
            #pragma unroll
            for (int nj2 = 0; nj2 < 2; nj2++) {
                adr = smem_u32(&sVh[kk + lr][wn0 + nj2 * 16 + lc * 8]);
                ldsm_x4t(adr, bvh[nj2][0], bvh[nj2][1], bvh[nj2][2], bvh[nj2][3]);
                adr = smem_u32(&sVl[kk + lr][wn0 + nj2 * 16 + lc * 8]);
                ldsm_x4t(adr, bvl[nj2][0], bvl[nj2][1], bvl[nj2][2], bvl[nj2][3]);
            }
            // trans [k][n] ldsm: n-half nh uses regs {r[2nh], r[2nh+1]}
            #pragma unroll
            for (int nj = 0; nj < 4; nj++) {
                int j2 = nj >> 1, hf = (nj & 1) * 2;
                mma_bf16(acc3[nj], aph, bvh[j2][hf], bvh[j2][hf + 1]);
                mma_bf16(acc3[nj], aph, bvl[j2][hf], bvl[j2][hf + 1]);
                mma_bf16(acc3[nj], apl, bvh[j2][hf], bvh[j2][hf + 1]);
            }
        }
    }

    // ctx epilogue: scale by 1/rowsum, write bf16 hi/lo
    #pragma unroll
    for (int nj = 0; nj < 4; nj++)
        #pragma unroll
        for (int rr = 0; rr < 2; rr++) {
            int rl = wm0 + g + rr * 8;
            float invs = rowS[rl];
            float v0 = acc3[nj][rr * 2] * invs;
            float v1 = acc3[nj][rr * 2 + 1] * invs;
            float h0 = __bfloat162float(__float2bfloat16_rn(v0));
            float h1 = __bfloat162float(__float2bfloat16_rn(v1));
            size_t off = (size_t)(t0 + rl) * 768 + hh * 64 + wn0 + nj * 8 + t4 * 2;
            *(u32*)(g_ch + off) = pack_bf16x2(v0, v1);
            *(u32*)(g_cl + off) = pack_bf16x2(v0 - h0, v1 - h1);
        }
}

// ---------------- launch ----------------------------------------------------
extern "C" void kernel_launch(void* const* d_in, const int* in_sizes, int n_in,
                              void* d_out, int out_size)
{
    const float* x     = (const float*)d_in[0];
    const float* Wq    = (const float*)d_in[1];
    const float* Wk    = (const float*)d_in[2];
    const float* Wv    = (const float*)d_in[3];
    const float* Wo    = (const float*)d_in[4];
    const float* gates = (const float*)d_in[5];
    const float* u     = (const float*)d_in[6];
    float* out  = (float*)d_out;
    float* attn = out + OUT_ELEMS;

    cudaFuncSetAttribute(attn_kernel, cudaFuncAttributeMaxDynamicSharedMemorySize, SMEM_BYTES);

    // split fp32 -> bf16 hi/lo
    cvt_kernel<<<(OUT_ELEMS/4 + 255)/256, 256>>>(x,  0, OUT_ELEMS/4);
    cvt_kernel<<<(EE*EE/4  + 255)/256, 256>>>(Wq, 1, EE*EE/4);
    cvt_kernel<<<(EE*EE/4  + 255)/256, 256>>>(Wk, 2, EE*EE/4);
    cvt_kernel<<<(EE*EE/4  + 255)/256, 256>>>(Wv, 3, EE*EE/4);
    cvt_kernel<<<(EE*EE/4  + 255)/256, 256>>>(Wo, 4, EE*EE/4);

    // QKV projections (tensor-core split-bf16, outputs bf16 hi/lo)
    dim3 gb(12, 32);
    bgemm_kernel<<<gb, 256>>>(nullptr, 0);
    bgemm_kernel<<<gb, 256>>>(nullptr, 1);
    bgemm_kernel<<<gb, 256>>>(nullptr, 2);

    // d bias from K (hi+lo reconstruct)
    dbias_kernel<<<12, 1024>>>(u);

    // banded gated attention (zero-fill + band + ctx hi/lo), tensor-core
    dim3 ga(64, 12, 1);
    attn_kernel<<<ga, 256, SMEM_BYTES>>>(gates, attn);

    // output projection (fp32 out)
    bgemm_kernel<<<gb, 256>>>(out, 3);
}

// round 13
// speedup vs baseline: 1.9940x; 1.2113x over previous
#include <cuda_runtime.h>
#include <cuda_bf16.h>
#include <math.h>

#define TT 4096
#define EE 768
#define HH 12
#define DD 64
#define WIN 512
#define OUT_ELEMS (TT*EE)                 // 3145728
#define ATTN_ELEMS ((size_t)HH*TT*TT)     // 201326592

typedef unsigned long long ull;
typedef unsigned int u32;

// cp.async helpers (16B)
#define CPA16(dst, src) asm volatile("cp.async.cg.shared.global [%0], [%1], 16;" :: "r"(dst), "l"(src))
#define CPC()  asm volatile("cp.async.commit_group;")
#define CPW0() asm volatile("cp.async.wait_group 0;" ::: "memory")

// ---------------- scratch (device globals: allocation-free) ----------------
__device__ __align__(16) float g_d[HH*TT];

// bf16 two-term split buffers
__device__ __align__(16) __nv_bfloat16 g_xh[TT*EE], g_xl[TT*EE];
__device__ __align__(16) __nv_bfloat16 g_Wh[4][EE*EE], g_Wl[4][EE*EE];
__device__ __align__(16) __nv_bfloat16 g_Qh[TT*EE], g_Ql[TT*EE];
__device__ __align__(16) __nv_bfloat16 g_Kh[TT*EE], g_Kl[TT*EE];
__device__ __align__(16) __nv_bfloat16 g_Vh[TT*EE], g_Vl[TT*EE];
__device__ __align__(16) __nv_bfloat16 g_ch[TT*EE], g_cl[TT*EE];   // ctx hi/lo

// ---------------- helpers ----------------------------------------------------
__device__ __forceinline__ u32 pack_bf16x2(float a, float b) {
    __nv_bfloat16 ha = __float2bfloat16_rn(a), hb = __float2bfloat16_rn(b);
    return ((u32)__bfloat16_as_ushort(hb) << 16) | __bfloat16_as_ushort(ha);
}
// fast exp on FMA pipe: exp(x) = 2^(x*log2e), poly deg-5, ~2e-7 rel err
__device__ __forceinline__ float fast_exp(float x) {
    float y = fmaxf(x * 1.4426950408889634f, -126.0f);
    float n = floorf(y);
    float f = y - n;
    float p = 1.8775767e-3f;
    p = fmaf(p, f, 8.9893397e-3f);
    p = fmaf(p, f, 5.5826318e-2f);
    p = fmaf(p, f, 2.4015361e-1f);
    p = fmaf(p, f, 6.9315308e-1f);
    p = fmaf(p, f, 1.0f);
    float s = __int_as_float(((int)n + 127) << 23);
    return p * s;
}

// ---------------- fp32 -> bf16 hi/lo split (single fused launch) ------------
#define XN4 (OUT_ELEMS/4)          // 786432
#define WN4 (EE*EE/4)              // 147456
#define CVT_TOTAL (XN4 + 4*WN4)    // 1376256
__global__ __launch_bounds__(256) void cvt_kernel(
    const float* __restrict__ x,  const float* __restrict__ Wq,
    const float* __restrict__ Wk, const float* __restrict__ Wv,
    const float* __restrict__ Wo)
{
    int i = blockIdx.x * 256 + threadIdx.x;
    if (i >= CVT_TOTAL) return;
    const float* src; __nv_bfloat16 *hi, *lo; int idx;
    if (i < XN4) { src = x; hi = g_xh; lo = g_xl; idx = i; }
    else {
        int j = i - XN4;
        int w = j / WN4;
        idx = j - w * WN4;
        src = (w == 0) ? Wq : (w == 1) ? Wk : (w == 2) ? Wv : Wo;
        hi = g_Wh[w]; lo = g_Wl[w];
    }
    float4 v = ((const float4*)src)[idx];
    float h0f = __bfloat162float(__float2bfloat16_rn(v.x));
    float h1f = __bfloat162float(__float2bfloat16_rn(v.y));
    float h2f = __bfloat162float(__float2bfloat16_rn(v.z));
    float h3f = __bfloat162float(__float2bfloat16_rn(v.w));
    uint2 hp, lp;
    hp.x = pack_bf16x2(v.x, v.y);
    hp.y = pack_bf16x2(v.z, v.w);
    lp.x = pack_bf16x2(v.x - h0f, v.y - h1f);
    lp.y = pack_bf16x2(v.z - h2f, v.w - h3f);
    ((uint2*)hi)[idx] = hp;
    ((uint2*)lo)[idx] = lp;
}

// ---------------- mma helpers ------------------------------------------------
__device__ __forceinline__ u32 smem_u32(const void* p) {
    return (u32)__cvta_generic_to_shared(p);
}
__device__ __forceinline__ void ldsm_x4(u32 addr, u32& r0, u32& r1, u32& r2, u32& r3) {
    asm volatile("ldmatrix.sync.aligned.m8n8.x4.shared.b16 {%0,%1,%2,%3}, [%4];"
        : "=r"(r0), "=r"(r1), "=r"(r2), "=r"(r3) : "r"(addr));
}
__device__ __forceinline__ void ldsm_x4t(u32 addr, u32& r0, u32& r1, u32& r2, u32& r3) {
    asm volatile("ldmatrix.sync.aligned.m8n8.x4.trans.shared.b16 {%0,%1,%2,%3}, [%4];"
        : "=r"(r0), "=r"(r1), "=r"(r2), "=r"(r3) : "r"(addr));
}
__device__ __forceinline__ void mma_bf16(float* d, const u32* a, u32 b0, u32 b1) {
    asm volatile(
        "mma.sync.aligned.m16n8k16.row.col.f32.bf16.bf16.f32 "
        "{%0,%1,%2,%3}, {%4,%5,%6,%7}, {%8,%9}, {%0,%1,%2,%3};"
        : "+f"(d[0]), "+f"(d[1]), "+f"(d[2]), "+f"(d[3])
        : "r"(a[0]), "r"(a[1]), "r"(a[2]), "r"(a[3]), "r"(b0), "r"(b1));
}

// ---------------- split-bf16 GEMM, cp.async double-buffered -----------------
// wsel -1 (QKV): wsel := blockIdx.z;  A=x, C -> g_{Q,K,V}{h,l}
// wsel  3:       A=ctx(hi/lo), W=Wo, C -> Cext (fp32)
#define LDA 40
#define LDB 72
#define A_BUF (128*LDA)   // 5120 bf16
#define B_BUF (32*LDB)    // 2304 bf16
#define GEMM_SMEM ((2*A_BUF*2 + 2*B_BUF*2) * 2)   // 59392 bytes
#define NKI 24
__global__ __launch_bounds__(256) void bgemm_kernel(float* __restrict__ Cext, int wsel)
{
    if (wsel < 0) wsel = blockIdx.z;
    const __nv_bfloat16 *Ah, *Al;
    const __nv_bfloat16 *Bh = g_Wh[wsel], *Bl = g_Wl[wsel];
    __nv_bfloat16 *Ch = nullptr, *Cl = nullptr;
    if (wsel < 3) {
        Ah = g_xh; Al = g_xl;
        Ch = (wsel == 0) ? g_Qh : (wsel == 1) ? g_Kh : g_Vh;
        Cl = (wsel == 0) ? g_Ql : (wsel == 1) ? g_Kl : g_Vl;
    } else {
        Ah = g_ch; Al = g_cl;
    }

    extern __shared__ __nv_bfloat16 smb[];
    __nv_bfloat16* bAh = smb;                 // [2][128][LDA]
    __nv_bfloat16* bAl = bAh + 2 * A_BUF;
    __nv_bfloat16* bBh = bAl + 2 * A_BUF;     // [2][32][LDB]
    __nv_bfloat16* bBl = bBh + 2 * B_BUF;

    int tid = threadIdx.x;
    int wid = tid >> 5, lane = tid & 31;
    int m0 = blockIdx.y * 128, n0 = blockIdx.x * 64;
    int wm0 = (wid >> 1) * 32, wn0 = (wid & 1) * 32;
    int lr = lane & 15, lc = lane >> 4;

    // per-thread load coordinates
    int ar0 = tid >> 2,            akc = (tid & 3) * 8;          // A chunk 1
    int ar1 = (tid + 256) >> 2,    akc1 = ((tid + 256) & 3) * 8; // A chunk 2
    int brow = tid >> 3,           bnc = (tid & 7) * 8;          // B chunk

    float acc[2][4][4];
    #pragma unroll
    for (int mi = 0; mi < 2; mi++)
        #pragma unroll
        for (int nj = 0; nj < 4; nj++)
            #pragma unroll
            for (int q = 0; q < 4; q++) acc[mi][nj][q] = 0.f;

    // prologue: load k-step 0 into buf 0
    {
        int k0 = 0;
        CPA16(smem_u32(bAh + ar0 * LDA + akc),  Ah + (size_t)(m0 + ar0) * 768 + k0 + akc);
        CPA16(smem_u32(bAh + ar1 * LDA + akc1), Ah + (size_t)(m0 + ar1) * 768 + k0 + akc1);
        CPA16(smem_u32(bAl + ar0 * LDA + akc),  Al + (size_t)(m0 + ar0) * 768 + k0 + akc);
        CPA16(smem_u32(bAl + ar1 * LDA + akc1), Al + (size_t)(m0 + ar1) * 768 + k0 + akc1);
        CPA16(smem_u32(bBh + brow * LDB + bnc), Bh + (size_t)(k0 + brow) * 768 + n0 + bnc);
        CPA16(smem_u32(bBl + brow * LDB + bnc), Bl + (size_t)(k0 + brow) * 768 + n0 + bnc);
        CPC();
    }

    int buf = 0;
    for (int ki = 0; ki < NKI; ki++) {
        CPW0();
        __syncthreads();
        if (ki + 1 < NKI) {
            int k0 = (ki + 1) * 32;
            int ob = (buf ^ 1);
            __nv_bfloat16* dAh = bAh + ob * A_BUF;
            __nv_bfloat16* dAl = bAl + ob * A_BUF;
            __nv_bfloat16* dBh = bBh + ob * B_BUF;
            __nv_bfloat16* dBl = bBl + ob * B_BUF;
            CPA16(smem_u32(dAh + ar0 * LDA + akc),  Ah + (size_t)(m0 + ar0) * 768 + k0 + akc);
            CPA16(smem_u32(dAh + ar1 * LDA + akc1), Ah + (size_t)(m0 + ar1) * 768 + k0 + akc1);
            CPA16(smem_u32(dAl + ar0 * LDA + akc),  Al + (size_t)(m0 + ar0) * 768 + k0 + akc);
            CPA16(smem_u32(dAl + ar1 * LDA + akc1), Al + (size_t)(m0 + ar1) * 768 + k0 + akc1);
            CPA16(smem_u32(dBh + brow * LDB + bnc), Bh + (size_t)(k0 + brow) * 768 + n0 + bnc);
            CPA16(smem_u32(dBl + brow * LDB + bnc), Bl + (size_t)(k0 + brow) * 768 + n0 + bnc);
            CPC();
        }

        const __nv_bfloat16* cAh = bAh + buf * A_BUF;
        const __nv_bfloat16* cAl = bAl + buf * A_BUF;
        const __nv_bfloat16* cBh = bBh + buf * B_BUF;
        const __nv_bfloat16* cBl = bBl + buf * B_BUF;

        #pragma unroll
        for (int kk = 0; kk < 32; kk += 16) {
            u32 ah[2][4], al[2][4], bh[2][4], bl[2][4];
            #pragma unroll
            for (int mi = 0; mi < 2; mi++) {
                u32 adr = smem_u32(cAh + (wm0 + mi * 16 + lr) * LDA + kk + lc * 8);
                ldsm_x4(adr, ah[mi][0], ah[mi][1], ah[mi][2], ah[mi][3]);
                adr = smem_u32(cAl + (wm0 + mi * 16 + lr) * LDA + kk + lc * 8);
                ldsm_x4(adr, al[mi][0], al[mi][1], al[mi][2], al[mi][3]);
            }
            #pragma unroll
            for (int nj2 = 0; nj2 < 2; nj2++) {
                u32 adr = smem_u32(cBh + (kk + lr) * LDB + wn0 + nj2 * 16 + lc * 8);
                ldsm_x4t(adr, bh[nj2][0], bh[nj2][1], bh[nj2][2], bh[nj2][3]);
                adr = smem_u32(cBl + (kk + lr) * LDB + wn0 + nj2 * 16 + lc * 8);
                ldsm_x4t(adr, bl[nj2][0], bl[nj2][1], bl[nj2][2], bl[nj2][3]);
            }
            #pragma unroll
            for (int mi = 0; mi < 2; mi++)
                #pragma unroll
                for (int nj = 0; nj < 4; nj++) {
                    int j2 = nj >> 1, hf = (nj & 1) * 2;
                    mma_bf16(acc[mi][nj], ah[mi], bh[j2][hf], bh[j2][hf + 1]);
                    mma_bf16(acc[mi][nj], ah[mi], bl[j2][hf], bl[j2][hf + 1]);
                    mma_bf16(acc[mi][nj], al[mi], bh[j2][hf], bh[j2][hf + 1]);
                }
        }
        buf ^= 1;
        __syncthreads();
    }

    int g = lane >> 2, t4 = lane & 3;
    #pragma unroll
    for (int mi = 0; mi < 2; mi++)
        #pragma unroll
        for (int nj = 0; nj < 4; nj++) {
            int row = m0 + wm0 + mi * 16 + g;
            int col = n0 + wn0 + nj * 8 + t4 * 2;
            if (wsel == 3) {
                *(float2*)&Cext[(size_t)row * 768 + col] =
                    make_float2(acc[mi][nj][0], acc[mi][nj][1]);
                *(float2*)&Cext[(size_t)(row + 8) * 768 + col] =
                    make_float2(acc[mi][nj][2], acc[mi][nj][3]);
            } else {
                #pragma unroll
                for (int rr = 0; rr < 2; rr++) {
                    float v0 = acc[mi][nj][rr * 2], v1 = acc[mi][nj][rr * 2 + 1];
                    float h0 = __bfloat162float(__float2bfloat16_rn(v0));
                    float h1 = __bfloat162float(__float2bfloat16_rn(v1));
                    size_t off = (size_t)(row + rr * 8) * 768 + col;
                    *(u32*)(Ch + off) = pack_bf16x2(v0, v1);
                    *(u32*)(Cl + off) = pack_bf16x2(v0 - h0, v1 - h1);
                }
            }
        }
}

// ---------------- d bias -----------------------------------------------------
__global__ __launch_bounds__(1024) void dbias_kernel(const float* __restrict__ u)
{
    int h = blockIdx.x, tid = threadIdx.x;
    __shared__ float su[64];
    __shared__ float red[32];
    if (tid < 64) su[tid] = u[h * 64 + tid];
    __syncthreads();

    float vals[4];
    float lsum = 0.f;
    #pragma unroll
    for (int j = 0; j < 4; j++) {
        int t = j * 1024 + tid;
        const __nv_bfloat162* kh = (const __nv_bfloat162*)(g_Kh + (size_t)t * 768 + h * 64);
        const __nv_bfloat162* kl = (const __nv_bfloat162*)(g_Kl + (size_t)t * 768 + h * 64);
        float dot = 0.f;
        #pragma unroll
        for (int q = 0; q < 32; q++) {
            float2 hv = __bfloat1622float2(kh[q]);
            float2 lv = __bfloat1622float2(kl[q]);
            dot += (hv.x + lv.x) * su[q * 2] + (hv.y + lv.y) * su[q * 2 + 1];
        }
        vals[j] = dot;
        lsum += dot;
    }
    #pragma unroll
    for (int o = 16; o > 0; o >>= 1) lsum += __shfl_xor_sync(0xffffffffu, lsum, o);
    if ((tid & 31) == 0) red[tid >> 5] = lsum;
    __syncthreads();
    if (tid < 32) {
        float v = red[tid];
        #pragma unroll
        for (int o = 16; o > 0; o >>= 1) v += __shfl_xor_sync(0xffffffffu, v, o);
        if (tid == 0) red[0] = v * (1.0f / 4096.0f);
    }
    __syncthreads();
    float mean = red[0];
    #pragma unroll
    for (int j = 0; j < 4; j++)
        g_d[h * 4096 + j * 1024 + tid] = vals[j] - mean;
}

// ---------------- attention: 64 query rows per block, tensor-core ----------
#define LW 580
#define TLD 72
#define SMEM_BYTES (64*LW*4 + 8*64*TLD*2 + 576*4 + 64*4)

__global__ __launch_bounds__(256) void attn_kernel(
    const float* __restrict__ gates, float* __restrict__ attn_out)
{
    extern __shared__ char smraw[];
    float* sL = (float*)smraw;                                  // 64*580 f32
    __nv_bfloat16 (*sQh)[TLD]  = (__nv_bfloat16(*)[TLD])(smraw + 64*LW*4);
    __nv_bfloat16 (*sQl)[TLD]  = sQh  + 64;
    __nv_bfloat16 (*sKqh)[TLD] = sQl  + 64;
    __nv_bfloat16 (*sKql)[TLD] = sKqh + 64;
    __nv_bfloat16 (*sKbh)[TLD] = sKql + 64;
    __nv_bfloat16 (*sKbl)[TLD] = sKbh + 64;
    __nv_bfloat16 (*sQbh)[TLD] = sKbl + 64;
    __nv_bfloat16 (*sQbl)[TLD] = sQbh + 64;
    float* sd   = (float*)(sQbl + 64);                          // 576
    float* rowS = sd + 576;                                     // 64

    __nv_bfloat16 (*sPh)[TLD] = sQh,  (*sPl)[TLD] = sQl;
    __nv_bfloat16 (*sVh)[TLD] = sKbh, (*sVl)[TLD] = sKbl;

    int hh = blockIdx.y;
    int t0 = blockIdx.x * 64;
    int tid = threadIdx.x;
    int wid = tid >> 5, lane = tid & 31;
    int sb = t0 - 512; if (sb < 0) sb = 0;
    int L = t0 + 64 - sb;

    // ---- fused zero-fill of out-of-band attn region (fire-and-forget) ----
    {
        const float4 z4 = make_float4(0.f, 0.f, 0.f, 0.f);
        size_t rowbase = (size_t)hh * TT * TT + (size_t)t0 * TT;
        int leftq = sb >> 2;
        int right0 = t0 + 64;
        int rightq = (TT - right0) >> 2;
        for (int r = 0; r < 64; r++) {
            float4* bp = (float4*)(attn_out + rowbase + (size_t)r * TT);
            for (int c = tid; c < leftq; c += 256) bp[c] = z4;
            float4* rp4 = (float4*)(attn_out + rowbase + (size_t)r * TT + right0);
            for (int c = tid; c < rightq; c += 256) rp4[c] = z4;
        }
    }

    // gate softmax
    float g0 = gates[hh * 3 + 0], g1 = gates[hh * 3 + 1], g2 = gates[hh * 3 + 2];
    float gm = fmaxf(g0, fmaxf(g1, g2));
    float e0 = fast_exp(g0 - gm), e1 = fast_exp(g1 - gm), e2 = fast_exp(g2 - gm);
    float gi = 1.0f / (e0 + e1 + e2);
    float wstd = e0 * gi, wrec = e1 * gi, wdisc = e2 * gi;

    // load query-row tiles (Q,K hi/lo) via cp.async + d band
    for (int i = tid; i < 64 * 8; i += 256) {
        int row = i >> 3;
        int c8 = (i & 7) * 8;
        size_t off = (size_t)(t0 + row) * 768 + hh * 64 + c8;
        CPA16(smem_u32(&sQh[row][c8]),  g_Qh + off);
        CPA16(smem_u32(&sQl[row][c8]),  g_Ql + off);
        CPA16(smem_u32(&sKqh[row][c8]), g_Kh + off);
        CPA16(smem_u32(&sKql[row][c8]), g_Kl + off);
    }
    CPC();
    for (int i = tid; i < L; i += 256) sd[i] = g_d[hh * 4096 + sb + i];
    CPW0();

    int wm0 = (wid >> 1) * 16, wn0 = (wid & 1) * 32;
    int lr = lane & 15, lc = lane >> 4;
    int g = lane >> 2, t4 = lane & 3;
    int kt_lo = sb >> 6, kt_hi = t0 >> 6;

    // ---- phase 1: banded logits via split-bf16 MMA ----
    for (int kt = kt_lo; kt <= kt_hi; kt++) {
        int s0 = kt * 64;
        __syncthreads();
        for (int i = tid; i < 64 * 8; i += 256) {
            int row = i >> 3;
            int c8 = (i & 7) * 8;
            size_t off = (size_t)(s0 + row) * 768 + hh * 64 + c8;
            CPA16(smem_u32(&sKbh[row][c8]), g_Kh + off);
            CPA16(smem_u32(&sKbl[row][c8]), g_Kl + off);
            CPA16(smem_u32(&sQbh[row][c8]), g_Qh + off);
            CPA16(smem_u32(&sQbl[row][c8]), g_Ql + off);
        }
        CPC(); CPW0();
        __syncthreads();

        float acc1[4][4], acc2[4][4];
        #pragma unroll
        for (int nj = 0; nj < 4; nj++)
            #pragma unroll
            for (int q = 0; q < 4; q++) { acc1[nj][q] = 0.f; acc2[nj][q] = 0.f; }

        #pragma unroll
        for (int kk = 0; kk < 64; kk += 16) {
            u32 aqh[4], aql[4], akh[4], akl[4];
            u32 adr = smem_u32(&sQh[wm0 + lr][kk + lc * 8]);
            ldsm_x4(adr, aqh[0], aqh[1], aqh[2], aqh[3]);
            adr = smem_u32(&sQl[wm0 + lr][kk + lc * 8]);
            ldsm_x4(adr, aql[0], aql[1], aql[2], aql[3]);
            adr = smem_u32(&sKqh[wm0 + lr][kk + lc * 8]);
            ldsm_x4(adr, akh[0], akh[1], akh[2], akh[3]);
            adr = smem_u32(&sKql[wm0 + lr][kk + lc * 8]);
            ldsm_x4(adr, akl[0], akl[1], akl[2], akl[3]);

            u32 bkh[2][4], bkl[2][4], bqh[2][4], bql[2][4];
            #pragma unroll
            for (int nj2 = 0; nj2 < 2; nj2++) {
                adr = smem_u32(&sKbh[wn0 + nj2 * 16 + lr][kk + lc * 8]);
                ldsm_x4(adr, bkh[nj2][0], bkh[nj2][1], bkh[nj2][2], bkh[nj2][3]);
                adr = smem_u32(&sKbl[wn0 + nj2 * 16 + lr][kk + lc * 8]);
                ldsm_x4(adr, bkl[nj2][0], bkl[nj2][1], bkl[nj2][2], bkl[nj2][3]);
                adr = smem_u32(&sQbh[wn0 + nj2 * 16 + lr][kk + lc * 8]);
                ldsm_x4(adr, bqh[nj2][0], bqh[nj2][1], bqh[nj2][2], bqh[nj2][3]);
                adr = smem_u32(&sQbl[wn0 + nj2 * 16 + lr][kk + lc * 8]);
                ldsm_x4(adr, bql[nj2][0], bql[nj2][1], bql[nj2][2], bql[nj2][3]);
            }
            #pragma unroll
            for (int nj = 0; nj < 4; nj++) {
                int j2 = nj >> 1, nh = nj & 1;
                mma_bf16(acc1[nj], aqh, bkh[j2][nh], bkh[j2][nh + 2]);
                mma_bf16(acc1[nj], aqh, bkl[j2][nh], bkl[j2][nh + 2]);
                mma_bf16(acc1[nj], aql, bkh[j2][nh], bkh[j2][nh + 2]);
                mma_bf16(acc2[nj], akh, bqh[j2][nh], bqh[j2][nh + 2]);
                mma_bf16(acc2[nj], akh, bql[j2][nh], bql[j2][nh + 2]);
                mma_bf16(acc2[nj], akl, bqh[j2][nh], bqh[j2][nh + 2]);
            }
        }

        int soff = s0 - sb;
        #pragma unroll
        for (int nj = 0; nj < 4; nj++)
            #pragma unroll
            for (int q = 0; q < 4; q++) {
                int rl = wm0 + g + (q >> 1) * 8;
                int cl = wn0 + nj * 8 + t4 * 2 + (q & 1);
                int t = t0 + rl, s = s0 + cl;
                float v;
                if (s <= t && (t - s) <= 512)
                    v = (wstd * acc1[nj][q] + wrec * acc2[nj][q]) * 0.125f + wdisc * sd[soff + cl];
                else
                    v = -1e30f;
                sL[rl * LW + soff + cl] = v;
            }
    }
    __syncthreads();

    // ---- phase 2a: per-row max + exp (in place) + sum; 4 threads/row ----
    {
        int row = tid >> 2, l4 = tid & 3;
        float* rp = sL + row * LW;
        float m = -1e30f;
        for (int c = l4; c < L; c += 4) m = fmaxf(m, rp[c]);
        m = fmaxf(m, __shfl_xor_sync(0xffffffffu, m, 1));
        m = fmaxf(m, __shfl_xor_sync(0xffffffffu, m, 2));
        float s = 0.f;
        for (int c = l4; c < L; c += 4) {
            float ev = fast_exp(rp[c] - m);
            rp[c] = ev;
            s += ev;
        }
        s += __shfl_xor_sync(0xffffffffu, s, 1);
        s += __shfl_xor_sync(0xffffffffu, s, 2);
        if (l4 == 0) rowS[row] = 1.0f / s;
    }
    __syncthreads();

    // ---- phase 2b: write normalized attn band (float4) ----
    {
        size_t base = (size_t)hh * TT * TT + (size_t)t0 * TT + sb;
        int L4 = L >> 2;
        for (int i = 0; i < 64; i++) {
            float invs = rowS[i];
            const float* rp = sL + i * LW;
            float4* op = (float4*)(attn_out + base + (size_t)i * TT);
            for (int c = tid; c < L4; c += 256) {
                float4 p = *(const float4*)(rp + c * 4);
                p.x *= invs; p.y *= invs; p.z *= invs; p.w *= invs;
                op[c] = p;
            }
        }
    }

    // ---- phase 3: ctx = P @ V via split-bf16 MMA ----
    float acc3[4][4];
    #pragma unroll
    for (int nj = 0; nj < 4; nj++)
        #pragma unroll
        for (int q = 0; q < 4; q++) acc3[nj][q] = 0.f;

    for (int kt = kt_lo; kt <= kt_hi; kt++) {
        int s0 = kt * 64;
        int soff = s0 - sb;
        __syncthreads();
        for (int i = tid; i < 64 * 8; i += 256) {
            int row = i >> 3;
            int c8 = (i & 7) * 8;
            size_t off = (size_t)(s0 + row) * 768 + hh * 64 + c8;
            CPA16(smem_u32(&sVh[row][c8]), g_Vh + off);
            CPA16(smem_u32(&sVl[row][c8]), g_Vl + off);
        }
        CPC();
        // stage P block (exp values) as bf16 hi/lo
        for (int i = tid; i < 64 * 32; i += 256) {
            int row = i >> 5;
            int c2 = (i & 31) * 2;
            float v0 = sL[row * LW + soff + c2];
            float v1 = sL[row * LW + soff + c2 + 1];
            float h0 = __bfloat162float(__float2bfloat16_rn(v0));
            float h1 = __bfloat162float(__float2bfloat16_rn(v1));
            *(u32*)&sPh[row][c2] = pack_bf16x2(v0, v1);
            *(u32*)&sPl[row][c2] = pack_bf16x2(v0 - h0, v1 - h1);
        }
        CPW0();
        __syncthreads();

        #pragma unroll
        for (int kk = 0; kk < 64; kk += 16) {
            u32 aph[4], apl[4];
            u32 adr = smem_u32(&sPh[wm0 + lr][kk + lc * 8]);
            ldsm_x4(adr, aph[0], aph[1], aph[2], aph[3]);
            adr = smem_u32(&sPl[wm0 + lr][kk + lc * 8]);
            ldsm_x4(adr, apl[0], apl[1], apl[2], apl[3]);
            u32 bvh[2][4], bvl[2][4];
            #pragma unroll
            for (int nj2 = 0; nj2 < 2; nj2++) {
                adr = smem_u32(&sVh[kk + lr][wn0 + nj2 * 16 + lc * 8]);
                ldsm_x4t(adr, bvh[nj2][0], bvh[nj2][1], bvh[nj2][2], bvh[nj2][3]);
                adr = smem_u32(&sVl[kk + lr][wn0 + nj2 * 16 + lc * 8]);
                ldsm_x4t(adr, bvl[nj2][0], bvl[nj2][1], bvl[nj2][2], bvl[nj2][3]);
            }
            #pragma unroll
            for (int nj = 0; nj < 4; nj++) {
                int j2 = nj >> 1, hf = (nj & 1) * 2;
                mma_bf16(acc3[nj], aph, bvh[j2][hf], bvh[j2][hf + 1]);
                mma_bf16(acc3[nj], aph, bvl[j2][hf], bvl[j2][hf + 1]);
                mma_bf16(acc3[nj], apl, bvh[j2][hf], bvh[j2][hf + 1]);
            }
        }
    }

    // ctx epilogue: scale by 1/rowsum, write bf16 hi/lo
    #pragma unroll
    for (int nj = 0; nj < 4; nj++)
        #pragma unroll
        for (int rr = 0; rr < 2; rr++) {
            int rl = wm0 + g + rr * 8;
            float invs = rowS[rl];
            float v0 = acc3[nj][rr * 2] * invs;
            float v1 = acc3[nj][rr * 2 + 1] * invs;
            float h0 = __bfloat162float(__float2bfloat16_rn(v0));
            float h1 = __bfloat162float(__float2bfloat16_rn(v1));
            size_t off = (size_t)(t0 + rl) * 768 + hh * 64 + wn0 + nj * 8 + t4 * 2;
            *(u32*)(g_ch + off) = pack_bf16x2(v0, v1);
            *(u32*)(g_cl + off) = pack_bf16x2(v0 - h0, v1 - h1);
        }
}

// ---------------- launch ----------------------------------------------------
extern "C" void kernel_launch(void* const* d_in, const int* in_sizes, int n_in,
                              void* d_out, int out_size)
{
    const float* x     = (const float*)d_in[0];
    const float* Wq    = (const float*)d_in[1];
    const float* Wk    = (const float*)d_in[2];
    const float* Wv    = (const float*)d_in[3];
    const float* Wo    = (const float*)d_in[4];
    const float* gates = (const float*)d_in[5];
    const float* u     = (const float*)d_in[6];
    float* out  = (float*)d_out;
    float* attn = out + OUT_ELEMS;

    cudaFuncSetAttribute(attn_kernel, cudaFuncAttributeMaxDynamicSharedMemorySize, SMEM_BYTES);
    cudaFuncSetAttribute(bgemm_kernel, cudaFuncAttributeMaxDynamicSharedMemorySize, GEMM_SMEM);

    // split fp32 -> bf16 hi/lo (one launch)
    cvt_kernel<<<(CVT_TOTAL + 255)/256, 256>>>(x, Wq, Wk, Wv, Wo);

    // QKV projections: one launch, z = wsel
    dim3 gq(12, 32, 3);
    bgemm_kernel<<<gq, 256, GEMM_SMEM>>>(nullptr, -1);

    // d bias from K (hi+lo reconstruct)
    dbias_kernel<<<12, 1024>>>(u);

    // banded gated attention
    dim3 ga(64, 12, 1);
    attn_kernel<<<ga, 256, SMEM_BYTES>>>(gates, attn);

    // output projection (fp32 out)
    dim3 go(12, 32, 1);
    bgemm_kernel<<<go, 256, GEMM_SMEM>>>(out, 3);
}

// round 14
// speedup vs baseline: 2.0877x; 1.0470x over previous
#include <cuda_runtime.h>
#include <cuda_bf16.h>
#include <math.h>

#define TT 4096
#define EE 768
#define HH 12
#define DD 64
#define WIN 512
#define OUT_ELEMS (TT*EE)                 // 3145728
#define ATTN_ELEMS ((size_t)HH*TT*TT)     // 201326592

typedef unsigned long long ull;
typedef unsigned int u32;

// cp.async helpers (16B)
#define CPA16(dst, src) asm volatile("cp.async.cg.shared.global [%0], [%1], 16;" :: "r"(dst), "l"(src))
#define CPC()  asm volatile("cp.async.commit_group;")
#define CPW0() asm volatile("cp.async.wait_group 0;" ::: "memory")
#define CPW1() asm volatile("cp.async.wait_group 1;" ::: "memory")

// ---------------- scratch (device globals: allocation-free) ----------------
__device__ __align__(16) float g_d[HH*TT];

// bf16 two-term split buffers
__device__ __align__(16) __nv_bfloat16 g_xh[TT*EE], g_xl[TT*EE];
__device__ __align__(16) __nv_bfloat16 g_Wh[4][EE*EE], g_Wl[4][EE*EE];
__device__ __align__(16) __nv_bfloat16 g_Qh[TT*EE], g_Ql[TT*EE];
__device__ __align__(16) __nv_bfloat16 g_Kh[TT*EE], g_Kl[TT*EE];
__device__ __align__(16) __nv_bfloat16 g_Vh[TT*EE], g_Vl[TT*EE];
__device__ __align__(16) __nv_bfloat16 g_ch[TT*EE], g_cl[TT*EE];   // ctx hi/lo

// ---------------- helpers ----------------------------------------------------
__device__ __forceinline__ u32 pack_bf16x2(float a, float b) {
    __nv_bfloat16 ha = __float2bfloat16_rn(a), hb = __float2bfloat16_rn(b);
    return ((u32)__bfloat16_as_ushort(hb) << 16) | __bfloat16_as_ushort(ha);
}
// fast exp on FMA pipe: exp(x) = 2^(x*log2e), poly deg-5, ~2e-7 rel err
__device__ __forceinline__ float fast_exp(float x) {
    float y = fmaxf(x * 1.4426950408889634f, -126.0f);
    float n = floorf(y);
    float f = y - n;
    float p = 1.8775767e-3f;
    p = fmaf(p, f, 8.9893397e-3f);
    p = fmaf(p, f, 5.5826318e-2f);
    p = fmaf(p, f, 2.4015361e-1f);
    p = fmaf(p, f, 6.9315308e-1f);
    p = fmaf(p, f, 1.0f);
    float s = __int_as_float(((int)n + 127) << 23);
    return p * s;
}

// ---------------- fp32 -> bf16 hi/lo split (single fused launch) ------------
#define XN4 (OUT_ELEMS/4)          // 786432
#define WN4 (EE*EE/4)              // 147456
#define CVT_TOTAL (XN4 + 4*WN4)    // 1376256
__global__ __launch_bounds__(256) void cvt_kernel(
    const float* __restrict__ x,  const float* __restrict__ Wq,
    const float* __restrict__ Wk, const float* __restrict__ Wv,
    const float* __restrict__ Wo)
{
    int i = blockIdx.x * 256 + threadIdx.x;
    if (i >= CVT_TOTAL) return;
    const float* src; __nv_bfloat16 *hi, *lo; int idx;
    if (i < XN4) { src = x; hi = g_xh; lo = g_xl; idx = i; }
    else {
        int j = i - XN4;
        int w = j / WN4;
        idx = j - w * WN4;
        src = (w == 0) ? Wq : (w == 1) ? Wk : (w == 2) ? Wv : Wo;
        hi = g_Wh[w]; lo = g_Wl[w];
    }
    float4 v = ((const float4*)src)[idx];
    float h0f = __bfloat162float(__float2bfloat16_rn(v.x));
    float h1f = __bfloat162float(__float2bfloat16_rn(v.y));
    float h2f = __bfloat162float(__float2bfloat16_rn(v.z));
    float h3f = __bfloat162float(__float2bfloat16_rn(v.w));
    uint2 hp, lp;
    hp.x = pack_bf16x2(v.x, v.y);
    hp.y = pack_bf16x2(v.z, v.w);
    lp.x = pack_bf16x2(v.x - h0f, v.y - h1f);
    lp.y = pack_bf16x2(v.z - h2f, v.w - h3f);
    ((uint2*)hi)[idx] = hp;
    ((uint2*)lo)[idx] = lp;
}

// ---------------- mma helpers ------------------------------------------------
__device__ __forceinline__ u32 smem_u32(const void* p) {
    return (u32)__cvta_generic_to_shared(p);
}
__device__ __forceinline__ void ldsm_x4(u32 addr, u32& r0, u32& r1, u32& r2, u32& r3) {
    asm volatile("ldmatrix.sync.aligned.m8n8.x4.shared.b16 {%0,%1,%2,%3}, [%4];"
        : "=r"(r0), "=r"(r1), "=r"(r2), "=r"(r3) : "r"(addr));
}
__device__ __forceinline__ void ldsm_x4t(u32 addr, u32& r0, u32& r1, u32& r2, u32& r3) {
    asm volatile("ldmatrix.sync.aligned.m8n8.x4.trans.shared.b16 {%0,%1,%2,%3}, [%4];"
        : "=r"(r0), "=r"(r1), "=r"(r2), "=r"(r3) : "r"(addr));
}
__device__ __forceinline__ void mma_bf16(float* d, const u32* a, u32 b0, u32 b1) {
    asm volatile(
        "mma.sync.aligned.m16n8k16.row.col.f32.bf16.bf16.f32 "
        "{%0,%1,%2,%3}, {%4,%5,%6,%7}, {%8,%9}, {%0,%1,%2,%3};"
        : "+f"(d[0]), "+f"(d[1]), "+f"(d[2]), "+f"(d[3])
        : "r"(a[0]), "r"(a[1]), "r"(a[2]), "r"(a[3]), "r"(b0), "r"(b1));
}

// ---------------- split-bf16 GEMM, cp.async double-buffered -----------------
#define LDA 40
#define LDB 72
#define A_BUF (128*LDA)
#define B_BUF (32*LDB)
#define GEMM_SMEM ((2*A_BUF*2 + 2*B_BUF*2) * 2)   // 59392 bytes
#define NKI 24
__global__ __launch_bounds__(256) void bgemm_kernel(float* __restrict__ Cext, int wsel)
{
    if (wsel < 0) wsel = blockIdx.z;
    const __nv_bfloat16 *Ah, *Al;
    const __nv_bfloat16 *Bh = g_Wh[wsel], *Bl = g_Wl[wsel];
    __nv_bfloat16 *Ch = nullptr, *Cl = nullptr;
    if (wsel < 3) {
        Ah = g_xh; Al = g_xl;
        Ch = (wsel == 0) ? g_Qh : (wsel == 1) ? g_Kh : g_Vh;
        Cl = (wsel == 0) ? g_Ql : (wsel == 1) ? g_Kl : g_Vl;
    } else {
        Ah = g_ch; Al = g_cl;
    }

    extern __shared__ __nv_bfloat16 smb[];
    __nv_bfloat16* bAh = smb;
    __nv_bfloat16* bAl = bAh + 2 * A_BUF;
    __nv_bfloat16* bBh = bAl + 2 * A_BUF;
    __nv_bfloat16* bBl = bBh + 2 * B_BUF;

    int tid = threadIdx.x;
    int wid = tid >> 5, lane = tid & 31;
    int m0 = blockIdx.y * 128, n0 = blockIdx.x * 64;
    int wm0 = (wid >> 1) * 32, wn0 = (wid & 1) * 32;
    int lr = lane & 15, lc = lane >> 4;

    int ar0 = tid >> 2,            akc = (tid & 3) * 8;
    int ar1 = (tid + 256) >> 2,    akc1 = ((tid + 256) & 3) * 8;
    int brow = tid >> 3,           bnc = (tid & 7) * 8;

    float acc[2][4][4];
    #pragma unroll
    for (int mi = 0; mi < 2; mi++)
        #pragma unroll
        for (int nj = 0; nj < 4; nj++)
            #pragma unroll
            for (int q = 0; q < 4; q++) acc[mi][nj][q] = 0.f;

    {
        int k0 = 0;
        CPA16(smem_u32(bAh + ar0 * LDA + akc),  Ah + (size_t)(m0 + ar0) * 768 + k0 + akc);
        CPA16(smem_u32(bAh + ar1 * LDA + akc1), Ah + (size_t)(m0 + ar1) * 768 + k0 + akc1);
        CPA16(smem_u32(bAl + ar0 * LDA + akc),  Al + (size_t)(m0 + ar0) * 768 + k0 + akc);
        CPA16(smem_u32(bAl + ar1 * LDA + akc1), Al + (size_t)(m0 + ar1) * 768 + k0 + akc1);
        CPA16(smem_u32(bBh + brow * LDB + bnc), Bh + (size_t)(k0 + brow) * 768 + n0 + bnc);
        CPA16(smem_u32(bBl + brow * LDB + bnc), Bl + (size_t)(k0 + brow) * 768 + n0 + bnc);
        CPC();
    }

    int buf = 0;
    for (int ki = 0; ki < NKI; ki++) {
        CPW0();
        __syncthreads();
        if (ki + 1 < NKI) {
            int k0 = (ki + 1) * 32;
            int ob = (buf ^ 1);
            __nv_bfloat16* dAh = bAh + ob * A_BUF;
            __nv_bfloat16* dAl = bAl + ob * A_BUF;
            __nv_bfloat16* dBh = bBh + ob * B_BUF;
            __nv_bfloat16* dBl = bBl + ob * B_BUF;
            CPA16(smem_u32(dAh + ar0 * LDA + akc),  Ah + (size_t)(m0 + ar0) * 768 + k0 + akc);
            CPA16(smem_u32(dAh + ar1 * LDA + akc1), Ah + (size_t)(m0 + ar1) * 768 + k0 + akc1);
            CPA16(smem_u32(dAl + ar0 * LDA + akc),  Al + (size_t)(m0 + ar0) * 768 + k0 + akc);
            CPA16(smem_u32(dAl + ar1 * LDA + akc1), Al + (size_t)(m0 + ar1) * 768 + k0 + akc1);
            CPA16(smem_u32(dBh + brow * LDB + bnc), Bh + (size_t)(k0 + brow) * 768 + n0 + bnc);
            CPA16(smem_u32(dBl + brow * LDB + bnc), Bl + (size_t)(k0 + brow) * 768 + n0 + bnc);
            CPC();
        }

        const __nv_bfloat16* cAh = bAh + buf * A_BUF;
        const __nv_bfloat16* cAl = bAl + buf * A_BUF;
        const __nv_bfloat16* cBh = bBh + buf * B_BUF;
        const __nv_bfloat16* cBl = bBl + buf * B_BUF;

        #pragma unroll
        for (int kk = 0; kk < 32; kk += 16) {
            u32 ah[2][4], al[2][4], bh[2][4], bl[2][4];
            #pragma unroll
            for (int mi = 0; mi < 2; mi++) {
                u32 adr = smem_u32(cAh + (wm0 + mi * 16 + lr) * LDA + kk + lc * 8);
                ldsm_x4(adr, ah[mi][0], ah[mi][1], ah[mi][2], ah[mi][3]);
                adr = smem_u32(cAl + (wm0 + mi * 16 + lr) * LDA + kk + lc * 8);
                ldsm_x4(adr, al[mi][0], al[mi][1], al[mi][2], al[mi][3]);
            }
            #pragma unroll
            for (int nj2 = 0; nj2 < 2; nj2++) {
                u32 adr = smem_u32(cBh + (kk + lr) * LDB + wn0 + nj2 * 16 + lc * 8);
                ldsm_x4t(adr, bh[nj2][0], bh[nj2][1], bh[nj2][2], bh[nj2][3]);
                adr = smem_u32(cBl + (kk + lr) * LDB + wn0 + nj2 * 16 + lc * 8);
                ldsm_x4t(adr, bl[nj2][0], bl[nj2][1], bl[nj2][2], bl[nj2][3]);
            }
            #pragma unroll
            for (int mi = 0; mi < 2; mi++)
                #pragma unroll
                for (int nj = 0; nj < 4; nj++) {
                    int j2 = nj >> 1, hf = (nj & 1) * 2;
                    mma_bf16(acc[mi][nj], ah[mi], bh[j2][hf], bh[j2][hf + 1]);
                    mma_bf16(acc[mi][nj], ah[mi], bl[j2][hf], bl[j2][hf + 1]);
                    mma_bf16(acc[mi][nj], al[mi], bh[j2][hf], bh[j2][hf + 1]);
                }
        }
        buf ^= 1;
        __syncthreads();
    }

    int g = lane >> 2, t4 = lane & 3;
    #pragma unroll
    for (int mi = 0; mi < 2; mi++)
        #pragma unroll
        for (int nj = 0; nj < 4; nj++) {
            int row = m0 + wm0 + mi * 16 + g;
            int col = n0 + wn0 + nj * 8 + t4 * 2;
            if (wsel == 3) {
                *(float2*)&Cext[(size_t)row * 768 + col] =
                    make_float2(acc[mi][nj][0], acc[mi][nj][1]);
                *(float2*)&Cext[(size_t)(row + 8) * 768 + col] =
                    make_float2(acc[mi][nj][2], acc[mi][nj][3]);
            } else {
                #pragma unroll
                for (int rr = 0; rr < 2; rr++) {
                    float v0 = acc[mi][nj][rr * 2], v1 = acc[mi][nj][rr * 2 + 1];
                    float h0 = __bfloat162float(__float2bfloat16_rn(v0));
                    float h1 = __bfloat162float(__float2bfloat16_rn(v1));
                    size_t off = (size_t)(row + rr * 8) * 768 + col;
                    *(u32*)(Ch + off) = pack_bf16x2(v0, v1);
                    *(u32*)(Cl + off) = pack_bf16x2(v0 - h0, v1 - h1);
                }
            }
        }
}

// ---------------- d bias -----------------------------------------------------
__global__ __launch_bounds__(1024) void dbias_kernel(const float* __restrict__ u)
{
    int h = blockIdx.x, tid = threadIdx.x;
    __shared__ float su[64];
    __shared__ float red[32];
    if (tid < 64) su[tid] = u[h * 64 + tid];
    __syncthreads();

    float vals[4];
    float lsum = 0.f;
    #pragma unroll
    for (int j = 0; j < 4; j++) {
        int t = j * 1024 + tid;
        const __nv_bfloat162* kh = (const __nv_bfloat162*)(g_Kh + (size_t)t * 768 + h * 64);
        const __nv_bfloat162* kl = (const __nv_bfloat162*)(g_Kl + (size_t)t * 768 + h * 64);
        float dot = 0.f;
        #pragma unroll
        for (int q = 0; q < 32; q++) {
            float2 hv = __bfloat1622float2(kh[q]);
            float2 lv = __bfloat1622float2(kl[q]);
            dot += (hv.x + lv.x) * su[q * 2] + (hv.y + lv.y) * su[q * 2 + 1];
        }
        vals[j] = dot;
        lsum += dot;
    }
    #pragma unroll
    for (int o = 16; o > 0; o >>= 1) lsum += __shfl_xor_sync(0xffffffffu, lsum, o);
    if ((tid & 31) == 0) red[tid >> 5] = lsum;
    __syncthreads();
    if (tid < 32) {
        float v = red[tid];
        #pragma unroll
        for (int o = 16; o > 0; o >>= 1) v += __shfl_xor_sync(0xffffffffu, v, o);
        if (tid == 0) red[0] = v * (1.0f / 4096.0f);
    }
    __syncthreads();
    float mean = red[0];
    #pragma unroll
    for (int j = 0; j < 4; j++)
        g_d[h * 4096 + j * 1024 + tid] = vals[j] - mean;
}

// ---------------- attention: recompute-softmax, no sL band buffer -----------
// smem: 10 bf16 tiles [64][72] (Q,K query hi/lo; Kb,Qb key hi/lo (reused as
// Ph,Pl); V hi/lo) + sd + (m,s) reduction scratch = 95.5 KB -> 2 CTAs/SM.
#define TLD 72
#define TILE_B (64*TLD)           // bf16 elements per tile
#define ATT_SMEM (10*TILE_B*2 + 576*4 + 256*4)

struct LogitsFrag { float a1[4][4]; float a2[4][4]; };

__device__ __forceinline__ void logits_mma(
    const __nv_bfloat16 (*sQh)[TLD], const __nv_bfloat16 (*sQl)[TLD],
    const __nv_bfloat16 (*sKqh)[TLD], const __nv_bfloat16 (*sKql)[TLD],
    const __nv_bfloat16 (*sKbh)[TLD], const __nv_bfloat16 (*sKbl)[TLD],
    const __nv_bfloat16 (*sQbh)[TLD], const __nv_bfloat16 (*sQbl)[TLD],
    int wm0, int wn0, int lr, int lc, LogitsFrag& F)
{
    #pragma unroll
    for (int nj = 0; nj < 4; nj++)
        #pragma unroll
        for (int q = 0; q < 4; q++) { F.a1[nj][q] = 0.f; F.a2[nj][q] = 0.f; }

    #pragma unroll
    for (int kk = 0; kk < 64; kk += 16) {
        u32 aqh[4], aql[4], akh[4], akl[4];
        u32 adr = smem_u32(&sQh[wm0 + lr][kk + lc * 8]);
        ldsm_x4(adr, aqh[0], aqh[1], aqh[2], aqh[3]);
        adr = smem_u32(&sQl[wm0 + lr][kk + lc * 8]);
        ldsm_x4(adr, aql[0], aql[1], aql[2], aql[3]);
        adr = smem_u32(&sKqh[wm0 + lr][kk + lc * 8]);
        ldsm_x4(adr, akh[0], akh[1], akh[2], akh[3]);
        adr = smem_u32(&sKql[wm0 + lr][kk + lc * 8]);
        ldsm_x4(adr, akl[0], akl[1], akl[2], akl[3]);

        u32 bkh[2][4], bkl[2][4], bqh[2][4], bql[2][4];
        #pragma unroll
        for (int nj2 = 0; nj2 < 2; nj2++) {
            adr = smem_u32(&sKbh[wn0 + nj2 * 16 + lr][kk + lc * 8]);
            ldsm_x4(adr, bkh[nj2][0], bkh[nj2][1], bkh[nj2][2], bkh[nj2][3]);
            adr = smem_u32(&sKbl[wn0 + nj2 * 16 + lr][kk + lc * 8]);
            ldsm_x4(adr, bkl[nj2][0], bkl[nj2][1], bkl[nj2][2], bkl[nj2][3]);
            adr = smem_u32(&sQbh[wn0 + nj2 * 16 + lr][kk + lc * 8]);
            ldsm_x4(adr, bqh[nj2][0], bqh[nj2][1], bqh[nj2][2], bqh[nj2][3]);
            adr = smem_u32(&sQbl[wn0 + nj2 * 16 + lr][kk + lc * 8]);
            ldsm_x4(adr, bql[nj2][0], bql[nj2][1], bql[nj2][2], bql[nj2][3]);
        }
        #pragma unroll
        for (int nj = 0; nj < 4; nj++) {
            int j2 = nj >> 1, nh = nj & 1;
            mma_bf16(F.a1[nj], aqh, bkh[j2][nh], bkh[j2][nh + 2]);
            mma_bf16(F.a1[nj], aqh, bkl[j2][nh], bkl[j2][nh + 2]);
            mma_bf16(F.a1[nj], aql, bkh[j2][nh], bkh[j2][nh + 2]);
            mma_bf16(F.a2[nj], akh, bqh[j2][nh], bqh[j2][nh + 2]);
            mma_bf16(F.a2[nj], akh, bql[j2][nh], bql[j2][nh + 2]);
            mma_bf16(F.a2[nj], akl, bqh[j2][nh], bqh[j2][nh + 2]);
        }
    }
}

__global__ __launch_bounds__(256, 2) void attn_kernel(
    const float* __restrict__ gates, float* __restrict__ attn_out)
{
    extern __shared__ char smraw[];
    __nv_bfloat16 (*sQh)[TLD]  = (__nv_bfloat16(*)[TLD])smraw;
    __nv_bfloat16 (*sQl)[TLD]  = sQh  + 64;
    __nv_bfloat16 (*sKqh)[TLD] = sQl  + 64;
    __nv_bfloat16 (*sKql)[TLD] = sKqh + 64;
    __nv_bfloat16 (*sKbh)[TLD] = sKql + 64;   // reused as Ph in pass B
    __nv_bfloat16 (*sKbl)[TLD] = sKbh + 64;   // reused as Pl
    __nv_bfloat16 (*sQbh)[TLD] = sKbl + 64;
    __nv_bfloat16 (*sQbl)[TLD] = sQbh + 64;
    __nv_bfloat16 (*sVh)[TLD]  = sQbl + 64;
    __nv_bfloat16 (*sVl)[TLD]  = sVh  + 64;
    float* sd    = (float*)(sVl + 64);        // 576
    float* sMred = sd + 576;                  // 128
    float* sSred = sMred + 128;               // 128

    __nv_bfloat16 (*sPh)[TLD] = sKbh, (*sPl)[TLD] = sKbl;

    int hh = blockIdx.y;
    int t0 = blockIdx.x * 64;
    int tid = threadIdx.x;
    int wid = tid >> 5, lane = tid & 31;
    int sb = t0 - 512; if (sb < 0) sb = 0;
    int L = t0 + 64 - sb;

    // ---- fused zero-fill of out-of-band attn region (fire-and-forget) ----
    {
        const float4 z4 = make_float4(0.f, 0.f, 0.f, 0.f);
        size_t rowbase = (size_t)hh * TT * TT + (size_t)t0 * TT;
        int leftq = sb >> 2;
        int right0 = t0 + 64;
        int rightq = (TT - right0) >> 2;
        for (int r = 0; r < 64; r++) {
            float4* bp = (float4*)(attn_out + rowbase + (size_t)r * TT);
            for (int c = tid; c < leftq; c += 256) bp[c] = z4;
            float4* rp4 = (float4*)(attn_out + rowbase + (size_t)r * TT + right0);
            for (int c = tid; c < rightq; c += 256) rp4[c] = z4;
        }
    }

    // gate softmax
    float g0 = gates[hh * 3 + 0], g1 = gates[hh * 3 + 1], g2 = gates[hh * 3 + 2];
    float gm = fmaxf(g0, fmaxf(g1, g2));
    float e0 = fast_exp(g0 - gm), e1 = fast_exp(g1 - gm), e2 = fast_exp(g2 - gm);
    float gi = 1.0f / (e0 + e1 + e2);
    float wstd = e0 * gi, wrec = e1 * gi, wdisc = e2 * gi;

    // load query-row tiles (Q,K hi/lo) via cp.async + d band
    for (int i = tid; i < 64 * 8; i += 256) {
        int row = i >> 3;
        int c8 = (i & 7) * 8;
        size_t off = (size_t)(t0 + row) * 768 + hh * 64 + c8;
        CPA16(smem_u32(&sQh[row][c8]),  g_Qh + off);
        CPA16(smem_u32(&sQl[row][c8]),  g_Ql + off);
        CPA16(smem_u32(&sKqh[row][c8]), g_Kh + off);
        CPA16(smem_u32(&sKql[row][c8]), g_Kl + off);
    }
    CPC();
    for (int i = tid; i < L; i += 256) sd[i] = g_d[hh * 4096 + sb + i];
    CPW0();

    int wm0 = (wid >> 1) * 16, wn0 = (wid & 1) * 32;
    int lr = lane & 15, lc = lane >> 4;
    int g = lane >> 2, t4 = lane & 3;
    int kt_lo = sb >> 6, kt_hi = t0 >> 6;
    int r0g = t0 + wm0 + g, r1g = r0g + 8;   // my two global rows

    LogitsFrag F;

    // ================= PASS A: online row max & sum ==================
    float m_run0 = -1e30f, m_run1 = -1e30f, s_run0 = 0.f, s_run1 = 0.f;

    for (int kt = kt_lo; kt <= kt_hi; kt++) {
        int s0 = kt * 64;
        __syncthreads();
        for (int i = tid; i < 64 * 8; i += 256) {
            int row = i >> 3;
            int c8 = (i & 7) * 8;
            size_t off = (size_t)(s0 + row) * 768 + hh * 64 + c8;
            CPA16(smem_u32(&sKbh[row][c8]), g_Kh + off);
            CPA16(smem_u32(&sKbl[row][c8]), g_Kl + off);
            CPA16(smem_u32(&sQbh[row][c8]), g_Qh + off);
            CPA16(smem_u32(&sQbl[row][c8]), g_Ql + off);
        }
        CPC(); CPW0();
        __syncthreads();

        logits_mma(sQh, sQl, sKqh, sKql, sKbh, sKbl, sQbh, sQbl, wm0, wn0, lr, lc, F);

        int soff = s0 - sb;
        float v[4][4];
        float vmax0 = -1e30f, vmax1 = -1e30f;
        #pragma unroll
        for (int nj = 0; nj < 4; nj++)
            #pragma unroll
            for (int q = 0; q < 4; q++) {
                int cl = wn0 + nj * 8 + t4 * 2 + (q & 1);
                int t = (q < 2) ? r0g : r1g;
                int s = s0 + cl;
                float vv;
                if (s <= t && (t - s) <= 512)
                    vv = (wstd * F.a1[nj][q] + wrec * F.a2[nj][q]) * 0.125f + wdisc * sd[soff + cl];
                else
                    vv = -1e30f;
                v[nj][q] = vv;
                if (q < 2) vmax0 = fmaxf(vmax0, vv); else vmax1 = fmaxf(vmax1, vv);
            }
        vmax0 = fmaxf(vmax0, __shfl_xor_sync(0xffffffffu, vmax0, 1));
        vmax0 = fmaxf(vmax0, __shfl_xor_sync(0xffffffffu, vmax0, 2));
        vmax1 = fmaxf(vmax1, __shfl_xor_sync(0xffffffffu, vmax1, 1));
        vmax1 = fmaxf(vmax1, __shfl_xor_sync(0xffffffffu, vmax1, 2));
        float mn0 = fmaxf(m_run0, vmax0), mn1 = fmaxf(m_run1, vmax1);
        float sum0 = 0.f, sum1 = 0.f;
        #pragma unroll
        for (int nj = 0; nj < 4; nj++)
            #pragma unroll
            for (int q = 0; q < 4; q++) {
                float e = fast_exp(v[nj][q] - ((q < 2) ? mn0 : mn1));
                if (q < 2) sum0 += e; else sum1 += e;
            }
        sum0 += __shfl_xor_sync(0xffffffffu, sum0, 1);
        sum0 += __shfl_xor_sync(0xffffffffu, sum0, 2);
        sum1 += __shfl_xor_sync(0xffffffffu, sum1, 1);
        sum1 += __shfl_xor_sync(0xffffffffu, sum1, 2);
        s_run0 = s_run0 * fast_exp(m_run0 - mn0) + sum0;
        s_run1 = s_run1 * fast_exp(m_run1 - mn1) + sum1;
        m_run0 = mn0; m_run1 = mn1;
    }

    // combine the two warps (wid, wid^1) that share rows
    if (t4 == 0) {
        sMred[wid * 16 + g]     = m_run0;
        sMred[wid * 16 + 8 + g] = m_run1;
        sSred[wid * 16 + g]     = s_run0;
        sSred[wid * 16 + 8 + g] = s_run1;
    }
    __syncthreads();
    float mf0, mf1, invs0, invs1;
    {
        int own = wid * 16, par = (wid ^ 1) * 16;
        float mA = sMred[own + g], mB = sMred[par + g];
        mf0 = fmaxf(mA, mB);
        float sf = sSred[own + g] * fast_exp(mA - mf0) + sSred[par + g] * fast_exp(mB - mf0);
        invs0 = 1.0f / sf;
        mA = sMred[own + 8 + g]; mB = sMred[par + 8 + g];
        mf1 = fmaxf(mA, mB);
        sf = sSred[own + 8 + g] * fast_exp(mA - mf1) + sSred[par + 8 + g] * fast_exp(mB - mf1);
        invs1 = 1.0f / sf;
    }

    // ================= PASS B: recompute, write attn, PV ==================
    float acc3[4][4];
    #pragma unroll
    for (int nj = 0; nj < 4; nj++)
        #pragma unroll
        for (int q = 0; q < 4; q++) acc3[nj][q] = 0.f;

    for (int kt = kt_lo; kt <= kt_hi; kt++) {
        int s0 = kt * 64;
        __syncthreads();
        // group 1: Kb/Qb ; group 2: V (into dedicated tiles)
        for (int i = tid; i < 64 * 8; i += 256) {
            int row = i >> 3;
            int c8 = (i & 7) * 8;
            size_t off = (size_t)(s0 + row) * 768 + hh * 64 + c8;
            CPA16(smem_u32(&sKbh[row][c8]), g_Kh + off);
            CPA16(smem_u32(&sKbl[row][c8]), g_Kl + off);
            CPA16(smem_u32(&sQbh[row][c8]), g_Qh + off);
            CPA16(smem_u32(&sQbl[row][c8]), g_Ql + off);
        }
        CPC();
        for (int i = tid; i < 64 * 8; i += 256) {
            int row = i >> 3;
            int c8 = (i & 7) * 8;
            size_t off = (size_t)(s0 + row) * 768 + hh * 64 + c8;
            CPA16(smem_u32(&sVh[row][c8]), g_Vh + off);
            CPA16(smem_u32(&sVl[row][c8]), g_Vl + off);
        }
        CPC();
        CPW1();   // Kb/Qb group done; V may still be in flight
        __syncthreads();

        logits_mma(sQh, sQl, sKqh, sKql, sKbh, sKbl, sQbh, sQbl, wm0, wn0, lr, lc, F);

        int soff = s0 - sb;
        float p[4][4];
        #pragma unroll
        for (int nj = 0; nj < 4; nj++)
            #pragma unroll
            for (int q = 0; q < 4; q++) {
                int cl = wn0 + nj * 8 + t4 * 2 + (q & 1);
                int t = (q < 2) ? r0g : r1g;
                int s = s0 + cl;
                float vv;
                if (s <= t && (t - s) <= 512)
                    vv = (wstd * F.a1[nj][q] + wrec * F.a2[nj][q]) * 0.125f + wdisc * sd[soff + cl];
                else
                    vv = -1e30f;
                p[nj][q] = fast_exp(vv - ((q < 2) ? mf0 : mf1)) * ((q < 2) ? invs0 : invs1);
            }

        // write normalized attn band directly from registers
        {
            size_t base = (size_t)hh * TT * TT;
            #pragma unroll
            for (int nj = 0; nj < 4; nj++) {
                int cg = s0 + wn0 + nj * 8 + t4 * 2;
                *(float2*)(attn_out + base + (size_t)r0g * TT + cg) = make_float2(p[nj][0], p[nj][1]);
                *(float2*)(attn_out + base + (size_t)r1g * TT + cg) = make_float2(p[nj][2], p[nj][3]);
            }
        }

        __syncthreads();   // all warps done reading Kb/Qb -> safe to overwrite as P

        // stage normalized P as bf16 hi/lo into sKb slots
        #pragma unroll
        for (int nj = 0; nj < 4; nj++) {
            int c = wn0 + nj * 8 + t4 * 2;
            float v0 = p[nj][0], v1 = p[nj][1];
            float h0 = __bfloat162float(__float2bfloat16_rn(v0));
            float h1 = __bfloat162float(__float2bfloat16_rn(v1));
            *(u32*)&sPh[wm0 + g][c] = pack_bf16x2(v0, v1);
            *(u32*)&sPl[wm0 + g][c] = pack_bf16x2(v0 - h0, v1 - h1);
            v0 = p[nj][2]; v1 = p[nj][3];
            h0 = __bfloat162float(__float2bfloat16_rn(v0));
            h1 = __bfloat162float(__float2bfloat16_rn(v1));
            *(u32*)&sPh[wm0 + 8 + g][c] = pack_bf16x2(v0, v1);
            *(u32*)&sPl[wm0 + 8 + g][c] = pack_bf16x2(v0 - h0, v1 - h1);
        }
        CPW0();   // V arrived
        __syncthreads();

        // PV MMA: A = P (normalized), B = V^T
        #pragma unroll
        for (int kk = 0; kk < 64; kk += 16) {
            u32 aph[4], apl[4];
            u32 adr = smem_u32(&sPh[wm0 + lr][kk + lc * 8]);
            ldsm_x4(adr, aph[0], aph[1], aph[2], aph[3]);
            adr = smem_u32(&sPl[wm0 + lr][kk + lc * 8]);
            ldsm_x4(adr, apl[0], apl[1], apl[2], apl[3]);
            u32 bvh[2][4], bvl[2][4];
            #pragma unroll
            for (int nj2 = 0; nj2 < 2; nj2++) {
                adr = smem_u32(&sVh[kk + lr][wn0 + nj2 * 16 + lc * 8]);
                ldsm_x4t(adr, bvh[nj2][0], bvh[nj2][1], bvh[nj2][2], bvh[nj2][3]);
                adr = smem_u32(&sVl[kk + lr][wn0 + nj2 * 16 + lc * 8]);
                ldsm_x4t(adr, bvl[nj2][0], bvl[nj2][1], bvl[nj2][2], bvl[nj2][3]);
            }
            #pragma unroll
            for (int nj = 0; nj < 4; nj++) {
                int j2 = nj >> 1, hf = (nj & 1) * 2;
                mma_bf16(acc3[nj], aph, bvh[j2][hf], bvh[j2][hf + 1]);
                mma_bf16(acc3[nj], aph, bvl[j2][hf], bvl[j2][hf + 1]);
                mma_bf16(acc3[nj], apl, bvh[j2][hf], bvh[j2][hf + 1]);
            }
        }
    }

    // ctx epilogue (already normalized): write bf16 hi/lo
    #pragma unroll
    for (int nj = 0; nj < 4; nj++)
        #pragma unroll
        for (int rr = 0; rr < 2; rr++) {
            int rl = wm0 + g + rr * 8;
            float v0 = acc3[nj][rr * 2];
            float v1 = acc3[nj][rr * 2 + 1];
            float h0 = __bfloat162float(__float2bfloat16_rn(v0));
            float h1 = __bfloat162float(__float2bfloat16_rn(v1));
            size_t off = (size_t)(t0 + rl) * 768 + hh * 64 + wn0 + nj * 8 + t4 * 2;
            *(u32*)(g_ch + off) = pack_bf16x2(v0, v1);
            *(u32*)(g_cl + off) = pack_bf16x2(v0 - h0, v1 - h1);
        }
}

// ---------------- launch ----------------------------------------------------
extern "C" void kernel_launch(void* const* d_in, const int* in_sizes, int n_in,
                              void* d_out, int out_size)
{
    const float* x     = (const float*)d_in[0];
    const float* Wq    = (const float*)d_in[1];
    const float* Wk    = (const float*)d_in[2];
    const float* Wv    = (const float*)d_in[3];
    const float* Wo    = (const float*)d_in[4];
    const float* gates = (const float*)d_in[5];
    const float* u     = (const float*)d_in[6];
    float* out  = (float*)d_out;
    float* attn = out + OUT_ELEMS;

    cudaFuncSetAttribute(attn_kernel, cudaFuncAttributeMaxDynamicSharedMemorySize, ATT_SMEM);
    cudaFuncSetAttribute(bgemm_kernel, cudaFuncAttributeMaxDynamicSharedMemorySize, GEMM_SMEM);

    // split fp32 -> bf16 hi/lo (one launch)
    cvt_kernel<<<(CVT_TOTAL + 255)/256, 256>>>(x, Wq, Wk, Wv, Wo);

    // QKV projections: one launch, z = wsel
    dim3 gq(12, 32, 3);
    bgemm_kernel<<<gq, 256, GEMM_SMEM>>>(nullptr, -1);

    // d bias from K (hi+lo reconstruct)
    dbias_kernel<<<12, 1024>>>(u);

    // banded gated attention (recompute softmax, 2 CTAs/SM)
    dim3 ga(64, 12, 1);
    attn_kernel<<<ga, 256, ATT_SMEM>>>(gates, attn);

    // output projection (fp32 out)
    dim3 go(12, 32, 1);
    bgemm_kernel<<<go, 256, GEMM_SMEM>>>(out, 3);
}

// round 15
// speedup vs baseline: 2.0964x; 1.0042x over previous
#include <cuda_runtime.h>
#include <cuda_bf16.h>
#include <math.h>

#define TT 4096
#define EE 768
#define HH 12
#define DD 64
#define WIN 512
#define OUT_ELEMS (TT*EE)                 // 3145728
#define ATTN_ELEMS ((size_t)HH*TT*TT)     // 201326592

typedef unsigned long long ull;
typedef unsigned int u32;

// cp.async helpers (16B)
#define CPA16(dst, src) asm volatile("cp.async.cg.shared.global [%0], [%1], 16;" :: "r"(dst), "l"(src))
#define CPC()  asm volatile("cp.async.commit_group;")
#define CPW0() asm volatile("cp.async.wait_group 0;" ::: "memory")
#define CPW1() asm volatile("cp.async.wait_group 1;" ::: "memory")

// ---------------- scratch (device globals: allocation-free) ----------------
__device__ __align__(16) float g_d[HH*TT];

// bf16 two-term split buffers
__device__ __align__(16) __nv_bfloat16 g_xh[TT*EE], g_xl[TT*EE];
__device__ __align__(16) __nv_bfloat16 g_Wh[4][EE*EE], g_Wl[4][EE*EE];
__device__ __align__(16) __nv_bfloat16 g_Qh[TT*EE], g_Ql[TT*EE];
__device__ __align__(16) __nv_bfloat16 g_Kh[TT*EE], g_Kl[TT*EE];
__device__ __align__(16) __nv_bfloat16 g_Vh[TT*EE], g_Vl[TT*EE];
__device__ __align__(16) __nv_bfloat16 g_ch[TT*EE], g_cl[TT*EE];   // ctx hi/lo

// ---------------- helpers ----------------------------------------------------
__device__ __forceinline__ u32 pack_bf16x2(float a, float b) {
    __nv_bfloat16 ha = __float2bfloat16_rn(a), hb = __float2bfloat16_rn(b);
    return ((u32)__bfloat16_as_ushort(hb) << 16) | __bfloat16_as_ushort(ha);
}
// fast exp on FMA pipe: exp(x) = 2^(x*log2e), poly deg-5, ~2e-7 rel err
__device__ __forceinline__ float fast_exp(float x) {
    float y = fmaxf(x * 1.4426950408889634f, -126.0f);
    float n = floorf(y);
    float f = y - n;
    float p = 1.8775767e-3f;
    p = fmaf(p, f, 8.9893397e-3f);
    p = fmaf(p, f, 5.5826318e-2f);
    p = fmaf(p, f, 2.4015361e-1f);
    p = fmaf(p, f, 6.9315308e-1f);
    p = fmaf(p, f, 1.0f);
    float s = __int_as_float(((int)n + 127) << 23);
    return p * s;
}

// ---------------- fp32 -> bf16 hi/lo split (single fused launch) ------------
#define XN4 (OUT_ELEMS/4)          // 786432
#define WN4 (EE*EE/4)              // 147456
#define CVT_TOTAL (XN4 + 4*WN4)    // 1376256
__global__ __launch_bounds__(256) void cvt_kernel(
    const float* __restrict__ x,  const float* __restrict__ Wq,
    const float* __restrict__ Wk, const float* __restrict__ Wv,
    const float* __restrict__ Wo)
{
    int i = blockIdx.x * 256 + threadIdx.x;
    if (i >= CVT_TOTAL) return;
    const float* src; __nv_bfloat16 *hi, *lo; int idx;
    if (i < XN4) { src = x; hi = g_xh; lo = g_xl; idx = i; }
    else {
        int j = i - XN4;
        int w = j / WN4;
        idx = j - w * WN4;
        src = (w == 0) ? Wq : (w == 1) ? Wk : (w == 2) ? Wv : Wo;
        hi = g_Wh[w]; lo = g_Wl[w];
    }
    float4 v = ((const float4*)src)[idx];
    float h0f = __bfloat162float(__float2bfloat16_rn(v.x));
    float h1f = __bfloat162float(__float2bfloat16_rn(v.y));
    float h2f = __bfloat162float(__float2bfloat16_rn(v.z));
    float h3f = __bfloat162float(__float2bfloat16_rn(v.w));
    uint2 hp, lp;
    hp.x = pack_bf16x2(v.x, v.y);
    hp.y = pack_bf16x2(v.z, v.w);
    lp.x = pack_bf16x2(v.x - h0f, v.y - h1f);
    lp.y = pack_bf16x2(v.z - h2f, v.w - h3f);
    ((uint2*)hi)[idx] = hp;
    ((uint2*)lo)[idx] = lp;
}

// ---------------- mma helpers ------------------------------------------------
__device__ __forceinline__ u32 smem_u32(const void* p) {
    return (u32)__cvta_generic_to_shared(p);
}
__device__ __forceinline__ void ldsm_x4(u32 addr, u32& r0, u32& r1, u32& r2, u32& r3) {
    asm volatile("ldmatrix.sync.aligned.m8n8.x4.shared.b16 {%0,%1,%2,%3}, [%4];"
        : "=r"(r0), "=r"(r1), "=r"(r2), "=r"(r3) : "r"(addr));
}
__device__ __forceinline__ void ldsm_x4t(u32 addr, u32& r0, u32& r1, u32& r2, u32& r3) {
    asm volatile("ldmatrix.sync.aligned.m8n8.x4.trans.shared.b16 {%0,%1,%2,%3}, [%4];"
        : "=r"(r0), "=r"(r1), "=r"(r2), "=r"(r3) : "r"(addr));
}
__device__ __forceinline__ void mma_bf16(float* d, const u32* a, u32 b0, u32 b1) {
    asm volatile(
        "mma.sync.aligned.m16n8k16.row.col.f32.bf16.bf16.f32 "
        "{%0,%1,%2,%3}, {%4,%5,%6,%7}, {%8,%9}, {%0,%1,%2,%3};"
        : "+f"(d[0]), "+f"(d[1]), "+f"(d[2]), "+f"(d[3])
        : "r"(a[0]), "r"(a[1]), "r"(a[2]), "r"(a[3]), "r"(b0), "r"(b1));
}

// ---------------- split-bf16 GEMM, cp.async double-buffered -----------------
#define LDA 40
#define LDB 72
#define A_BUF (128*LDA)
#define B_BUF (32*LDB)
#define GEMM_SMEM ((2*A_BUF*2 + 2*B_BUF*2) * 2)   // 59392 bytes
#define NKI 24
__global__ __launch_bounds__(256) void bgemm_kernel(float* __restrict__ Cext, int wsel)
{
    if (wsel < 0) wsel = blockIdx.z;
    const __nv_bfloat16 *Ah, *Al;
    const __nv_bfloat16 *Bh = g_Wh[wsel], *Bl = g_Wl[wsel];
    __nv_bfloat16 *Ch = nullptr, *Cl = nullptr;
    if (wsel < 3) {
        Ah = g_xh; Al = g_xl;
        Ch = (wsel == 0) ? g_Qh : (wsel == 1) ? g_Kh : g_Vh;
        Cl = (wsel == 0) ? g_Ql : (wsel == 1) ? g_Kl : g_Vl;
    } else {
        Ah = g_ch; Al = g_cl;
    }

    extern __shared__ __nv_bfloat16 smb[];
    __nv_bfloat16* bAh = smb;
    __nv_bfloat16* bAl = bAh + 2 * A_BUF;
    __nv_bfloat16* bBh = bAl + 2 * A_BUF;
    __nv_bfloat16* bBl = bBh + 2 * B_BUF;

    int tid = threadIdx.x;
    int wid = tid >> 5, lane = tid & 31;
    int m0 = blockIdx.y * 128, n0 = blockIdx.x * 64;
    int wm0 = (wid >> 1) * 32, wn0 = (wid & 1) * 32;
    int lr = lane & 15, lc = lane >> 4;

    int ar0 = tid >> 2,            akc = (tid & 3) * 8;
    int ar1 = (tid + 256) >> 2,    akc1 = ((tid + 256) & 3) * 8;
    int brow = tid >> 3,           bnc = (tid & 7) * 8;

    float acc[2][4][4];
    #pragma unroll
    for (int mi = 0; mi < 2; mi++)
        #pragma unroll
        for (int nj = 0; nj < 4; nj++)
            #pragma unroll
            for (int q = 0; q < 4; q++) acc[mi][nj][q] = 0.f;

    {
        int k0 = 0;
        CPA16(smem_u32(bAh + ar0 * LDA + akc),  Ah + (size_t)(m0 + ar0) * 768 + k0 + akc);
        CPA16(smem_u32(bAh + ar1 * LDA + akc1), Ah + (size_t)(m0 + ar1) * 768 + k0 + akc1);
        CPA16(smem_u32(bAl + ar0 * LDA + akc),  Al + (size_t)(m0 + ar0) * 768 + k0 + akc);
        CPA16(smem_u32(bAl + ar1 * LDA + akc1), Al + (size_t)(m0 + ar1) * 768 + k0 + akc1);
        CPA16(smem_u32(bBh + brow * LDB + bnc), Bh + (size_t)(k0 + brow) * 768 + n0 + bnc);
        CPA16(smem_u32(bBl + brow * LDB + bnc), Bl + (size_t)(k0 + brow) * 768 + n0 + bnc);
        CPC();
    }

    int buf = 0;
    for (int ki = 0; ki < NKI; ki++) {
        CPW0();
        __syncthreads();
        if (ki + 1 < NKI) {
            int k0 = (ki + 1) * 32;
            int ob = (buf ^ 1);
            __nv_bfloat16* dAh = bAh + ob * A_BUF;
            __nv_bfloat16* dAl = bAl + ob * A_BUF;
            __nv_bfloat16* dBh = bBh + ob * B_BUF;
            __nv_bfloat16* dBl = bBl + ob * B_BUF;
            CPA16(smem_u32(dAh + ar0 * LDA + akc),  Ah + (size_t)(m0 + ar0) * 768 + k0 + akc);
            CPA16(smem_u32(dAh + ar1 * LDA + akc1), Ah + (size_t)(m0 + ar1) * 768 + k0 + akc1);
            CPA16(smem_u32(dAl + ar0 * LDA + akc),  Al + (size_t)(m0 + ar0) * 768 + k0 + akc);
            CPA16(smem_u32(dAl + ar1 * LDA + akc1), Al + (size_t)(m0 + ar1) * 768 + k0 + akc1);
            CPA16(smem_u32(dBh + brow * LDB + bnc), Bh + (size_t)(k0 + brow) * 768 + n0 + bnc);
            CPA16(smem_u32(dBl + brow * LDB + bnc), Bl + (size_t)(k0 + brow) * 768 + n0 + bnc);
            CPC();
        }

        const __nv_bfloat16* cAh = bAh + buf * A_BUF;
        const __nv_bfloat16* cAl = bAl + buf * A_BUF;
        const __nv_bfloat16* cBh = bBh + buf * B_BUF;
        const __nv_bfloat16* cBl = bBl + buf * B_BUF;

        #pragma unroll
        for (int kk = 0; kk < 32; kk += 16) {
            u32 ah[2][4], al[2][4], bh[2][4], bl[2][4];
            #pragma unroll
            for (int mi = 0; mi < 2; mi++) {
                u32 adr = smem_u32(cAh + (wm0 + mi * 16 + lr) * LDA + kk + lc * 8);
                ldsm_x4(adr, ah[mi][0], ah[mi][1], ah[mi][2], ah[mi][3]);
                adr = smem_u32(cAl + (wm0 + mi * 16 + lr) * LDA + kk + lc * 8);
                ldsm_x4(adr, al[mi][0], al[mi][1], al[mi][2], al[mi][3]);
            }
            #pragma unroll
            for (int nj2 = 0; nj2 < 2; nj2++) {
                u32 adr = smem_u32(cBh + (kk + lr) * LDB + wn0 + nj2 * 16 + lc * 8);
                ldsm_x4t(adr, bh[nj2][0], bh[nj2][1], bh[nj2][2], bh[nj2][3]);
                adr = smem_u32(cBl + (kk + lr) * LDB + wn0 + nj2 * 16 + lc * 8);
                ldsm_x4t(adr, bl[nj2][0], bl[nj2][1], bl[nj2][2], bl[nj2][3]);
            }
            #pragma unroll
            for (int mi = 0; mi < 2; mi++)
                #pragma unroll
                for (int nj = 0; nj < 4; nj++) {
                    int j2 = nj >> 1, hf = (nj & 1) * 2;
                    mma_bf16(acc[mi][nj], ah[mi], bh[j2][hf], bh[j2][hf + 1]);
                    mma_bf16(acc[mi][nj], ah[mi], bl[j2][hf], bl[j2][hf + 1]);
                    mma_bf16(acc[mi][nj], al[mi], bh[j2][hf], bh[j2][hf + 1]);
                }
        }
        buf ^= 1;
        __syncthreads();
    }

    int g = lane >> 2, t4 = lane & 3;
    #pragma unroll
    for (int mi = 0; mi < 2; mi++)
        #pragma unroll
        for (int nj = 0; nj < 4; nj++) {
            int row = m0 + wm0 + mi * 16 + g;
            int col = n0 + wn0 + nj * 8 + t4 * 2;
            if (wsel == 3) {
                *(float2*)&Cext[(size_t)row * 768 + col] =
                    make_float2(acc[mi][nj][0], acc[mi][nj][1]);
                *(float2*)&Cext[(size_t)(row + 8) * 768 + col] =
                    make_float2(acc[mi][nj][2], acc[mi][nj][3]);
            } else {
                #pragma unroll
                for (int rr = 0; rr < 2; rr++) {
                    float v0 = acc[mi][nj][rr * 2], v1 = acc[mi][nj][rr * 2 + 1];
                    float h0 = __bfloat162float(__float2bfloat16_rn(v0));
                    float h1 = __bfloat162float(__float2bfloat16_rn(v1));
                    size_t off = (size_t)(row + rr * 8) * 768 + col;
                    *(u32*)(Ch + off) = pack_bf16x2(v0, v1);
                    *(u32*)(Cl + off) = pack_bf16x2(v0 - h0, v1 - h1);
                }
            }
        }
}

// ---------------- d bias -----------------------------------------------------
__global__ __launch_bounds__(1024) void dbias_kernel(const float* __restrict__ u)
{
    int h = blockIdx.x, tid = threadIdx.x;
    __shared__ float su[64];
    __shared__ float red[32];
    if (tid < 64) su[tid] = u[h * 64 + tid];
    __syncthreads();

    float vals[4];
    float lsum = 0.f;
    #pragma unroll
    for (int j = 0; j < 4; j++) {
        int t = j * 1024 + tid;
        const __nv_bfloat162* kh = (const __nv_bfloat162*)(g_Kh + (size_t)t * 768 + h * 64);
        const __nv_bfloat162* kl = (const __nv_bfloat162*)(g_Kl + (size_t)t * 768 + h * 64);
        float dot = 0.f;
        #pragma unroll
        for (int q = 0; q < 32; q++) {
            float2 hv = __bfloat1622float2(kh[q]);
            float2 lv = __bfloat1622float2(kl[q]);
            dot += (hv.x + lv.x) * su[q * 2] + (hv.y + lv.y) * su[q * 2 + 1];
        }
        vals[j] = dot;
        lsum += dot;
    }
    #pragma unroll
    for (int o = 16; o > 0; o >>= 1) lsum += __shfl_xor_sync(0xffffffffu, lsum, o);
    if ((tid & 31) == 0) red[tid >> 5] = lsum;
    __syncthreads();
    if (tid < 32) {
        float v = red[tid];
        #pragma unroll
        for (int o = 16; o > 0; o >>= 1) v += __shfl_xor_sync(0xffffffffu, v, o);
        if (tid == 0) red[0] = v * (1.0f / 4096.0f);
    }
    __syncthreads();
    float mean = red[0];
    #pragma unroll
    for (int j = 0; j < 4; j++)
        g_d[h * 4096 + j * 1024 + tid] = vals[j] - mean;
}

// ---------------- attention: recompute-softmax, no sL band buffer -----------
// smem: 10 bf16 tiles [64][72] (Q,K query hi/lo; Kb,Qb key hi/lo (reused as
// Ph,Pl); V hi/lo) + sd + (m,s) reduction scratch = 95.5 KB -> 2 CTAs/SM.
#define TLD 72
#define TILE_B (64*TLD)           // bf16 elements per tile
#define ATT_SMEM (10*TILE_B*2 + 576*4 + 256*4)

struct LogitsFrag { float a1[4][4]; float a2[4][4]; };

__device__ __forceinline__ void logits_mma(
    const __nv_bfloat16 (*sQh)[TLD], const __nv_bfloat16 (*sQl)[TLD],
    const __nv_bfloat16 (*sKqh)[TLD], const __nv_bfloat16 (*sKql)[TLD],
    const __nv_bfloat16 (*sKbh)[TLD], const __nv_bfloat16 (*sKbl)[TLD],
    const __nv_bfloat16 (*sQbh)[TLD], const __nv_bfloat16 (*sQbl)[TLD],
    int wm0, int wn0, int lr, int lc, LogitsFrag& F)
{
    #pragma unroll
    for (int nj = 0; nj < 4; nj++)
        #pragma unroll
        for (int q = 0; q < 4; q++) { F.a1[nj][q] = 0.f; F.a2[nj][q] = 0.f; }

    #pragma unroll
    for (int kk = 0; kk < 64; kk += 16) {
        u32 aqh[4], aql[4], akh[4], akl[4];
        u32 adr = smem_u32(&sQh[wm0 + lr][kk + lc * 8]);
        ldsm_x4(adr, aqh[0], aqh[1], aqh[2], aqh[3]);
        adr = smem_u32(&sQl[wm0 + lr][kk + lc * 8]);
        ldsm_x4(adr, aql[0], aql[1], aql[2], aql[3]);
        adr = smem_u32(&sKqh[wm0 + lr][kk + lc * 8]);
        ldsm_x4(adr, akh[0], akh[1], akh[2], akh[3]);
        adr = smem_u32(&sKql[wm0 + lr][kk + lc * 8]);
        ldsm_x4(adr, akl[0], akl[1], akl[2], akl[3]);

        u32 bkh[2][4], bkl[2][4], bqh[2][4], bql[2][4];
        #pragma unroll
        for (int nj2 = 0; nj2 < 2; nj2++) {
            adr = smem_u32(&sKbh[wn0 + nj2 * 16 + lr][kk + lc * 8]);
            ldsm_x4(adr, bkh[nj2][0], bkh[nj2][1], bkh[nj2][2], bkh[nj2][3]);
            adr = smem_u32(&sKbl[wn0 + nj2 * 16 + lr][kk + lc * 8]);
            ldsm_x4(adr, bkl[nj2][0], bkl[nj2][1], bkl[nj2][2], bkl[nj2][3]);
            adr = smem_u32(&sQbh[wn0 + nj2 * 16 + lr][kk + lc * 8]);
            ldsm_x4(adr, bqh[nj2][0], bqh[nj2][1], bqh[nj2][2], bqh[nj2][3]);
            adr = smem_u32(&sQbl[wn0 + nj2 * 16 + lr][kk + lc * 8]);
            ldsm_x4(adr, bql[nj2][0], bql[nj2][1], bql[nj2][2], bql[nj2][3]);
        }
        #pragma unroll
        for (int nj = 0; nj < 4; nj++) {
            int j2 = nj >> 1, nh = nj & 1;
            mma_bf16(F.a1[nj], aqh, bkh[j2][nh], bkh[j2][nh + 2]);
            mma_bf16(F.a1[nj], aqh, bkl[j2][nh], bkl[j2][nh + 2]);
            mma_bf16(F.a1[nj], aql, bkh[j2][nh], bkh[j2][nh + 2]);
            mma_bf16(F.a2[nj], akh, bqh[j2][nh], bqh[j2][nh + 2]);
            mma_bf16(F.a2[nj], akh, bql[j2][nh], bql[j2][nh + 2]);
            mma_bf16(F.a2[nj], akl, bqh[j2][nh], bqh[j2][nh + 2]);
        }
    }
}

__global__ __launch_bounds__(256, 2) void attn_kernel(
    const float* __restrict__ gates, float* __restrict__ attn_out)
{
    extern __shared__ char smraw[];
    __nv_bfloat16 (*sQh)[TLD]  = (__nv_bfloat16(*)[TLD])smraw;
    __nv_bfloat16 (*sQl)[TLD]  = sQh  + 64;
    __nv_bfloat16 (*sKqh)[TLD] = sQl  + 64;
    __nv_bfloat16 (*sKql)[TLD] = sKqh + 64;
    __nv_bfloat16 (*sKbh)[TLD] = sKql + 64;   // reused as Ph in pass B
    __nv_bfloat16 (*sKbl)[TLD] = sKbh + 64;   // reused as Pl
    __nv_bfloat16 (*sQbh)[TLD] = sKbl + 64;
    __nv_bfloat16 (*sQbl)[TLD] = sQbh + 64;
    __nv_bfloat16 (*sVh)[TLD]  = sQbl + 64;
    __nv_bfloat16 (*sVl)[TLD]  = sVh  + 64;
    float* sd    = (float*)(sVl + 64);        // 576
    float* sMred = sd + 576;                  // 128
    float* sSred = sMred + 128;               // 128

    __nv_bfloat16 (*sPh)[TLD] = sKbh, (*sPl)[TLD] = sKbl;

    int hh = blockIdx.y;
    int t0 = blockIdx.x * 64;
    int tid = threadIdx.x;
    int wid = tid >> 5, lane = tid & 31;
    int sb = t0 - 512; if (sb < 0) sb = 0;
    int L = t0 + 64 - sb;

    // ---- fused zero-fill of out-of-band attn region (fire-and-forget) ----
    {
        const float4 z4 = make_float4(0.f, 0.f, 0.f, 0.f);
        size_t rowbase = (size_t)hh * TT * TT + (size_t)t0 * TT;
        int leftq = sb >> 2;
        int right0 = t0 + 64;
        int rightq = (TT - right0) >> 2;
        for (int r = 0; r < 64; r++) {
            float4* bp = (float4*)(attn_out + rowbase + (size_t)r * TT);
            for (int c = tid; c < leftq; c += 256) bp[c] = z4;
            float4* rp4 = (float4*)(attn_out + rowbase + (size_t)r * TT + right0);
            for (int c = tid; c < rightq; c += 256) rp4[c] = z4;
        }
    }

    // gate softmax
    float g0 = gates[hh * 3 + 0], g1 = gates[hh * 3 + 1], g2 = gates[hh * 3 + 2];
    float gm = fmaxf(g0, fmaxf(g1, g2));
    float e0 = fast_exp(g0 - gm), e1 = fast_exp(g1 - gm), e2 = fast_exp(g2 - gm);
    float gi = 1.0f / (e0 + e1 + e2);
    float wstd = e0 * gi, wrec = e1 * gi, wdisc = e2 * gi;

    // load query-row tiles (Q,K hi/lo) via cp.async + d band
    for (int i = tid; i < 64 * 8; i += 256) {
        int row = i >> 3;
        int c8 = (i & 7) * 8;
        size_t off = (size_t)(t0 + row) * 768 + hh * 64 + c8;
        CPA16(smem_u32(&sQh[row][c8]),  g_Qh + off);
        CPA16(smem_u32(&sQl[row][c8]),  g_Ql + off);
        CPA16(smem_u32(&sKqh[row][c8]), g_Kh + off);
        CPA16(smem_u32(&sKql[row][c8]), g_Kl + off);
    }
    CPC();
    for (int i = tid; i < L; i += 256) sd[i] = g_d[hh * 4096 + sb + i];
    CPW0();

    int wm0 = (wid >> 1) * 16, wn0 = (wid & 1) * 32;
    int lr = lane & 15, lc = lane >> 4;
    int g = lane >> 2, t4 = lane & 3;
    int kt_lo = sb >> 6, kt_hi = t0 >> 6;
    int r0g = t0 + wm0 + g, r1g = r0g + 8;   // my two global rows

    LogitsFrag F;

    // ================= PASS A: online row max & sum ==================
    float m_run0 = -1e30f, m_run1 = -1e30f, s_run0 = 0.f, s_run1 = 0.f;

    for (int kt = kt_lo; kt <= kt_hi; kt++) {
        int s0 = kt * 64;
        __syncthreads();
        for (int i = tid; i < 64 * 8; i += 256) {
            int row = i >> 3;
            int c8 = (i & 7) * 8;
            size_t off = (size_t)(s0 + row) * 768 + hh * 64 + c8;
            CPA16(smem_u32(&sKbh[row][c8]), g_Kh + off);
            CPA16(smem_u32(&sKbl[row][c8]), g_Kl + off);
            CPA16(smem_u32(&sQbh[row][c8]), g_Qh + off);
            CPA16(smem_u32(&sQbl[row][c8]), g_Ql + off);
        }
        CPC(); CPW0();
        __syncthreads();

        logits_mma(sQh, sQl, sKqh, sKql, sKbh, sKbl, sQbh, sQbl, wm0, wn0, lr, lc, F);

        int soff = s0 - sb;
        float v[4][4];
        float vmax0 = -1e30f, vmax1 = -1e30f;
        #pragma unroll
        for (int nj = 0; nj < 4; nj++)
            #pragma unroll
            for (int q = 0; q < 4; q++) {
                int cl = wn0 + nj * 8 + t4 * 2 + (q & 1);
                int t = (q < 2) ? r0g : r1g;
                int s = s0 + cl;
                float vv;
                if (s <= t && (t - s) <= 512)
                    vv = (wstd * F.a1[nj][q] + wrec * F.a2[nj][q]) * 0.125f + wdisc * sd[soff + cl];
                else
                    vv = -1e30f;
                v[nj][q] = vv;
                if (q < 2) vmax0 = fmaxf(vmax0, vv); else vmax1 = fmaxf(vmax1, vv);
            }
        vmax0 = fmaxf(vmax0, __shfl_xor_sync(0xffffffffu, vmax0, 1));
        vmax0 = fmaxf(vmax0, __shfl_xor_sync(0xffffffffu, vmax0, 2));
        vmax1 = fmaxf(vmax1, __shfl_xor_sync(0xffffffffu, vmax1, 1));
        vmax1 = fmaxf(vmax1, __shfl_xor_sync(0xffffffffu, vmax1, 2));
        float mn0 = fmaxf(m_run0, vmax0), mn1 = fmaxf(m_run1, vmax1);
        float sum0 = 0.f, sum1 = 0.f;
        #pragma unroll
        for (int nj = 0; nj < 4; nj++)
            #pragma unroll
            for (int q = 0; q < 4; q++) {
                float e = fast_exp(v[nj][q] - ((q < 2) ? mn0 : mn1));
                if (q < 2) sum0 += e; else sum1 += e;
            }
        sum0 += __shfl_xor_sync(0xffffffffu, sum0, 1);
        sum0 += __shfl_xor_sync(0xffffffffu, sum0, 2);
        sum1 += __shfl_xor_sync(0xffffffffu, sum1, 1);
        sum1 += __shfl_xor_sync(0xffffffffu, sum1, 2);
        s_run0 = s_run0 * fast_exp(m_run0 - mn0) + sum0;
        s_run1 = s_run1 * fast_exp(m_run1 - mn1) + sum1;
        m_run0 = mn0; m_run1 = mn1;
    }

    // combine the two warps (wid, wid^1) that share rows
    if (t4 == 0) {
        sMred[wid * 16 + g]     = m_run0;
        sMred[wid * 16 + 8 + g] = m_run1;
        sSred[wid * 16 + g]     = s_run0;
        sSred[wid * 16 + 8 + g] = s_run1;
    }
    __syncthreads();
    float mf0, mf1, invs0, invs1;
    {
        int own = wid * 16, par = (wid ^ 1) * 16;
        float mA = sMred[own + g], mB = sMred[par + g];
        mf0 = fmaxf(mA, mB);
        float sf = sSred[own + g] * fast_exp(mA - mf0) + sSred[par + g] * fast_exp(mB - mf0);
        invs0 = 1.0f / sf;
        mA = sMred[own + 8 + g]; mB = sMred[par + 8 + g];
        mf1 = fmaxf(mA, mB);
        sf = sSred[own + 8 + g] * fast_exp(mA - mf1) + sSred[par + 8 + g] * fast_exp(mB - mf1);
        invs1 = 1.0f / sf;
    }

    // ================= PASS B: recompute, write attn, PV ==================
    float acc3[4][4];
    #pragma unroll
    for (int nj = 0; nj < 4; nj++)
        #pragma unroll
        for (int q = 0; q < 4; q++) acc3[nj][q] = 0.f;

    for (int kt = kt_lo; kt <= kt_hi; kt++) {
        int s0 = kt * 64;
        __syncthreads();
        // group 1: Kb/Qb ; group 2: V (into dedicated tiles)
        for (int i = tid; i < 64 * 8; i += 256) {
            int row = i >> 3;
            int c8 = (i & 7) * 8;
            size_t off = (size_t)(s0 + row) * 768 + hh * 64 + c8;
            CPA16(smem_u32(&sKbh[row][c8]), g_Kh + off);
            CPA16(smem_u32(&sKbl[row][c8]), g_Kl + off);
            CPA16(smem_u32(&sQbh[row][c8]), g_Qh + off);
            CPA16(smem_u32(&sQbl[row][c8]), g_Ql + off);
        }
        CPC();
        for (int i = tid; i < 64 * 8; i += 256) {
            int row = i >> 3;
            int c8 = (i & 7) * 8;
            size_t off = (size_t)(s0 + row) * 768 + hh * 64 + c8;
            CPA16(smem_u32(&sVh[row][c8]), g_Vh + off);
            CPA16(smem_u32(&sVl[row][c8]), g_Vl + off);
        }
        CPC();
        CPW1();   // Kb/Qb group done; V may still be in flight
        __syncthreads();

        logits_mma(sQh, sQl, sKqh, sKql, sKbh, sKbl, sQbh, sQbl, wm0, wn0, lr, lc, F);

        int soff = s0 - sb;
        float p[4][4];
        #pragma unroll
        for (int nj = 0; nj < 4; nj++)
            #pragma unroll
            for (int q = 0; q < 4; q++) {
                int cl = wn0 + nj * 8 + t4 * 2 + (q & 1);
                int t = (q < 2) ? r0g : r1g;
                int s = s0 + cl;
                float vv;
                if (s <= t && (t - s) <= 512)
                    vv = (wstd * F.a1[nj][q] + wrec * F.a2[nj][q]) * 0.125f + wdisc * sd[soff + cl];
                else
                    vv = -1e30f;
                p[nj][q] = fast_exp(vv - ((q < 2) ? mf0 : mf1)) * ((q < 2) ? invs0 : invs1);
            }

        // write normalized attn band directly from registers
        {
            size_t base = (size_t)hh * TT * TT;
            #pragma unroll
            for (int nj = 0; nj < 4; nj++) {
                int cg = s0 + wn0 + nj * 8 + t4 * 2;
                *(float2*)(attn_out + base + (size_t)r0g * TT + cg) = make_float2(p[nj][0], p[nj][1]);
                *(float2*)(attn_out + base + (size_t)r1g * TT + cg) = make_float2(p[nj][2], p[nj][3]);
            }
        }

        __syncthreads();   // all warps done reading Kb/Qb -> safe to overwrite as P

        // stage normalized P as bf16 hi/lo into sKb slots
        #pragma unroll
        for (int nj = 0; nj < 4; nj++) {
            int c = wn0 + nj * 8 + t4 * 2;
            float v0 = p[nj][0], v1 = p[nj][1];
            float h0 = __bfloat162float(__float2bfloat16_rn(v0));
            float h1 = __bfloat162float(__float2bfloat16_rn(v1));
            *(u32*)&sPh[wm0 + g][c] = pack_bf16x2(v0, v1);
            *(u32*)&sPl[wm0 + g][c] = pack_bf16x2(v0 - h0, v1 - h1);
            v0 = p[nj][2]; v1 = p[nj][3];
            h0 = __bfloat162float(__float2bfloat16_rn(v0));
            h1 = __bfloat162float(__float2bfloat16_rn(v1));
            *(u32*)&sPh[wm0 + 8 + g][c] = pack_bf16x2(v0, v1);
            *(u32*)&sPl[wm0 + 8 + g][c] = pack_bf16x2(v0 - h0, v1 - h1);
        }
        CPW0();   // V arrived
        __syncthreads();

        // PV MMA: A = P (normalized), B = V^T
        #pragma unroll
        for (int kk = 0; kk < 64; kk += 16) {
            u32 aph[4], apl[4];
            u32 adr = smem_u32(&sPh[wm0 + lr][kk + lc * 8]);
            ldsm_x4(adr, aph[0], aph[1], aph[2], aph[3]);
            adr = smem_u32(&sPl[wm0 + lr][kk + lc * 8]);
            ldsm_x4(adr, apl[0], apl[1], apl[2], apl[3]);
            u32 bvh[2][4], bvl[2][4];
            #pragma unroll
            for (int nj2 = 0; nj2 < 2; nj2++) {
                adr = smem_u32(&sVh[kk + lr][wn0 + nj2 * 16 + lc * 8]);
                ldsm_x4t(adr, bvh[nj2][0], bvh[nj2][1], bvh[nj2][2], bvh[nj2][3]);
                adr = smem_u32(&sVl[kk + lr][wn0 + nj2 * 16 + lc * 8]);
                ldsm_x4t(adr, bvl[nj2][0], bvl[nj2][1], bvl[nj2][2], bvl[nj2][3]);
            }
            #pragma unroll
            for (int nj = 0; nj < 4; nj++) {
                int j2 = nj >> 1, hf = (nj & 1) * 2;
                mma_bf16(acc3[nj], aph, bvh[j2][hf], bvh[j2][hf + 1]);
                mma_bf16(acc3[nj], aph, bvl[j2][hf], bvl[j2][hf + 1]);
                mma_bf16(acc3[nj], apl, bvh[j2][hf], bvh[j2][hf + 1]);
            }
        }
    }

    // ctx epilogue (already normalized): write bf16 hi/lo
    #pragma unroll
    for (int nj = 0; nj < 4; nj++)
        #pragma unroll
        for (int rr = 0; rr < 2; rr++) {
            int rl = wm0 + g + rr * 8;
            float v0 = acc3[nj][rr * 2];
            float v1 = acc3[nj][rr * 2 + 1];
            float h0 = __bfloat162float(__float2bfloat16_rn(v0));
            float h1 = __bfloat162float(__float2bfloat16_rn(v1));
            size_t off = (size_t)(t0 + rl) * 768 + hh * 64 + wn0 + nj * 8 + t4 * 2;
            *(u32*)(g_ch + off) = pack_bf16x2(v0, v1);
            *(u32*)(g_cl + off) = pack_bf16x2(v0 - h0, v1 - h1);
        }
}

// ---------------- launch ----------------------------------------------------
extern "C" void kernel_launch(void* const* d_in, const int* in_sizes, int n_in,
                              void* d_out, int out_size)
{
    const float* x     = (const float*)d_in[0];
    const float* Wq    = (const float*)d_in[1];
    const float* Wk    = (const float*)d_in[2];
    const float* Wv    = (const float*)d_in[3];
    const float* Wo    = (const float*)d_in[4];
    const float* gates = (const float*)d_in[5];
    const float* u     = (const float*)d_in[6];
    float* out  = (float*)d_out;
    float* attn = out + OUT_ELEMS;

    cudaFuncSetAttribute(attn_kernel, cudaFuncAttributeMaxDynamicSharedMemorySize, ATT_SMEM);
    cudaFuncSetAttribute(bgemm_kernel, cudaFuncAttributeMaxDynamicSharedMemorySize, GEMM_SMEM);

    // split fp32 -> bf16 hi/lo (one launch)
    cvt_kernel<<<(CVT_TOTAL + 255)/256, 256>>>(x, Wq, Wk, Wv, Wo);

    // QKV projections: one launch, z = wsel
    dim3 gq(12, 32, 3);
    bgemm_kernel<<<gq, 256, GEMM_SMEM>>>(nullptr, -1);

    // d bias from K (hi+lo reconstruct)
    dbias_kernel<<<12, 1024>>>(u);

    // banded gated attention (recompute softmax, 2 CTAs/SM)
    dim3 ga(64, 12, 1);
    attn_kernel<<<ga, 256, ATT_SMEM>>>(gates, attn);

    // output projection (fp32 out)
    dim3 go(12, 32, 1);
    bgemm_kernel<<<go, 256, GEMM_SMEM>>>(out, 3);
}